// round 2
// baseline (speedup 1.0000x reference)
#include <cuda_runtime.h>
#include <math.h>

// Problem constants
#define TOK   4096      // B*S
#define DIM   1024      // D == R
#define SEQ   2048
#define NBATCH 2
#define NH    8
#define DHEAD 128
#define NEXP  8         // NI == NO
#define NPROC 32
#define TOPK  3
#define KTOT  8192      // NEXP * DIM

// ---------------------------------------------------------------------------
// Scratch (device globals — no runtime allocation allowed)
// ---------------------------------------------------------------------------
__device__ float g_h  [TOK * DIM];
__device__ float g_Q  [TOK * DIM];
__device__ float g_Kc [TOK * DIM];
__device__ float g_V  [TOK * DIM];
__device__ float g_O  [TOK * DIM];
__device__ float g_inw [TOK * NEXP];
__device__ float g_outw[TOK * NEXP];
__device__ int   g_pidx[TOK * TOPK];

// ---------------------------------------------------------------------------
// Router: 48 logits per token (8 in / 32 proc / 8 out), softmax8 x2 + top-3
// One block per token, 128 threads (4 warps).
// ---------------------------------------------------------------------------
__global__ void router_kernel(const float* __restrict__ act,
                              const float* __restrict__ Wi,
                              const float* __restrict__ Wp,
                              const float* __restrict__ Wo,
                              float* __restrict__ inw,
                              int*   __restrict__ pidx,
                              float* __restrict__ outw)
{
    int t    = blockIdx.x;
    int tid  = threadIdx.x;
    int lane = tid & 31, warp = tid >> 5;
    __shared__ float xs[DIM];
    __shared__ float lg[48];

    const float* xr = act + (size_t)t * DIM;
    for (int i = tid; i < DIM; i += 128) xs[i] = xr[i];
    __syncthreads();

    for (int l = warp; l < 48; l += 4) {
        const float* wr = (l < 8) ? (Wi + (size_t)l * DIM)
                        : (l < 40) ? (Wp + (size_t)(l - 8) * DIM)
                                   : (Wo + (size_t)(l - 40) * DIM);
        float s = 0.f;
        for (int d = lane; d < DIM; d += 32) s += xs[d] * wr[d];
        #pragma unroll
        for (int off = 16; off > 0; off >>= 1)
            s += __shfl_xor_sync(0xffffffffu, s, off);
        if (lane == 0) lg[l] = s;
    }
    __syncthreads();

    if (tid == 0) {
        // softmax over in-logits [0..8)
        float m = lg[0];
        for (int i = 1; i < 8; i++) m = fmaxf(m, lg[i]);
        float e[8], sum = 0.f;
        for (int i = 0; i < 8; i++) { e[i] = expf(lg[i] - m); sum += e[i]; }
        for (int i = 0; i < 8; i++) inw[t * 8 + i] = e[i] / sum;

        // top-3 over proc logits [8..40): descending, ties -> lowest index
        bool used[NPROC];
        for (int n = 0; n < NPROC; n++) used[n] = false;
        for (int r = 0; r < TOPK; r++) {
            float best = -INFINITY; int bi = 0;
            for (int n = 0; n < NPROC; n++)
                if (!used[n] && lg[8 + n] > best) { best = lg[8 + n]; bi = n; }
            used[bi] = true;
            pidx[t * TOPK + r] = bi;
        }

        // softmax over out-logits [40..48)
        m = lg[40];
        for (int i = 1; i < 8; i++) m = fmaxf(m, lg[40 + i]);
        sum = 0.f;
        for (int i = 0; i < 8; i++) { e[i] = expf(lg[40 + i] - m); sum += e[i]; }
        for (int i = 0; i < 8; i++) outw[t * 8 + i] = e[i] / sum;
    }
}

// ---------------------------------------------------------------------------
// Mixture GEMM:  out[t, n] = sum_{k<8192} (wgt[t, k>>10] * act[t, k&1023]) * W[k, n]
// Tiles: 128x128x16, 256 threads, 8x8 microtile per thread, fp32.
// Double-buffered SMEM; A is generated on the fly (scaled activation row).
// ---------------------------------------------------------------------------
__global__ __launch_bounds__(256)
void circuit_gemm_kernel(const float* __restrict__ act,   // [4096,1024]
                         const float* __restrict__ W,     // [8192,1024] flat
                         const float* __restrict__ wgt,   // [4096,8]
                         float* __restrict__ out)         // [4096,1024]
{
    __shared__ float As[2][16][128];
    __shared__ float Bs[2][16][128];

    int tid = threadIdx.x;
    int bm = blockIdx.y * 128;
    int bn = blockIdx.x * 128;

    int am  = tid >> 1;            // 0..127 : token row within tile
    int ak  = (tid & 1) * 8;       // 0 or 8 : k offset within tile
    int arow = bm + am;
    const float* actp = act + (size_t)arow * DIM;
    const float* wgtp = wgt + (size_t)arow * NEXP;

    int bk = tid >> 5;             // 0..7 : B-tile row pair base (handles 2 rows)
    int bc = (tid & 31) * 4;       // column within B-tile row
    const float* Wp = W + bn + bc;

    int ty = tid >> 4;             // 0..15 row group
    int tx = tid & 15;             // 0..15 col group

    float acc[8][8];
    #pragma unroll
    for (int i = 0; i < 8; i++)
        #pragma unroll
        for (int j = 0; j < 8; j++) acc[i][j] = 0.f;

    // ---- preload tile 0 into buffer 0 ----
    {
        float scale = wgtp[0];
        float4 a0 = *(const float4*)(actp + ak);
        float4 a1 = *(const float4*)(actp + ak + 4);
        As[0][ak + 0][am] = a0.x * scale;  As[0][ak + 1][am] = a0.y * scale;
        As[0][ak + 2][am] = a0.z * scale;  As[0][ak + 3][am] = a0.w * scale;
        As[0][ak + 4][am] = a1.x * scale;  As[0][ak + 5][am] = a1.y * scale;
        As[0][ak + 6][am] = a1.z * scale;  As[0][ak + 7][am] = a1.w * scale;
        *(float4*)&Bs[0][bk    ][bc] = *(const float4*)(Wp + (size_t)(bk    ) * DIM);
        *(float4*)&Bs[0][bk + 8][bc] = *(const float4*)(Wp + (size_t)(bk + 8) * DIM);
    }
    __syncthreads();

    int buf = 0;
    for (int k0 = 0; k0 < KTOT; k0 += 16, buf ^= 1) {
        int kn = k0 + 16;
        float4 pa0, pa1, pb0, pb1;
        float pscale = 0.f;
        if (kn < KTOT) {
            pscale = wgtp[kn >> 10];
            int d0 = (kn & (DIM - 1)) + ak;
            pa0 = *(const float4*)(actp + d0);
            pa1 = *(const float4*)(actp + d0 + 4);
            pb0 = *(const float4*)(Wp + (size_t)(kn + bk    ) * DIM);
            pb1 = *(const float4*)(Wp + (size_t)(kn + bk + 8) * DIM);
        }

        // ---- compute on current buffer ----
        #pragma unroll
        for (int kk = 0; kk < 16; kk++) {
            float ra[8], rb[8];
            *(float4*)&ra[0] = *(const float4*)&As[buf][kk][ty * 8];
            *(float4*)&ra[4] = *(const float4*)&As[buf][kk][ty * 8 + 4];
            *(float4*)&rb[0] = *(const float4*)&Bs[buf][kk][tx * 8];
            *(float4*)&rb[4] = *(const float4*)&Bs[buf][kk][tx * 8 + 4];
            #pragma unroll
            for (int i = 0; i < 8; i++)
                #pragma unroll
                for (int j = 0; j < 8; j++)
                    acc[i][j] += ra[i] * rb[j];
        }

        // ---- store prefetched tile into other buffer ----
        if (kn < KTOT) {
            int nb = buf ^ 1;
            As[nb][ak + 0][am] = pa0.x * pscale;  As[nb][ak + 1][am] = pa0.y * pscale;
            As[nb][ak + 2][am] = pa0.z * pscale;  As[nb][ak + 3][am] = pa0.w * pscale;
            As[nb][ak + 4][am] = pa1.x * pscale;  As[nb][ak + 5][am] = pa1.y * pscale;
            As[nb][ak + 6][am] = pa1.z * pscale;  As[nb][ak + 7][am] = pa1.w * pscale;
            *(float4*)&Bs[nb][bk    ][bc] = pb0;
            *(float4*)&Bs[nb][bk + 8][bc] = pb1;
        }
        __syncthreads();
    }

    // ---- epilogue ----
    #pragma unroll
    for (int i = 0; i < 8; i++) {
        float* orow = out + (size_t)(bm + ty * 8 + i) * DIM + bn + tx * 8;
        *(float4*)(orow + 0) = make_float4(acc[i][0], acc[i][1], acc[i][2], acc[i][3]);
        *(float4*)(orow + 4) = make_float4(acc[i][4], acc[i][5], acc[i][6], acc[i][7]);
    }
}

// ---------------------------------------------------------------------------
// Householder reflections: h -= 2 (h.v)/(v.v + 1e-8) v, 3x per token, in order.
// One block per token, 256 threads (4 elems/thread).
// ---------------------------------------------------------------------------
__global__ void householder_kernel(float* __restrict__ hbuf,
                                   const float* __restrict__ vproc,  // [32,1024]
                                   const int* __restrict__ pidx)
{
    int t = blockIdx.x, tid = threadIdx.x;
    int lane = tid & 31, warp = tid >> 5;
    float* hr = hbuf + (size_t)t * DIM;

    float hv[4];
    #pragma unroll
    for (int i = 0; i < 4; i++) hv[i] = hr[tid + 256 * i];

    __shared__ float sred[16];

    for (int rfl = 0; rfl < TOPK; rfl++) {
        int idx = pidx[t * TOPK + rfl];
        const float* v = vproc + (size_t)idx * DIM;
        float vr[4];
        float d1 = 0.f, d2 = 0.f;
        #pragma unroll
        for (int i = 0; i < 4; i++) {
            vr[i] = v[tid + 256 * i];
            d1 += hv[i] * vr[i];
            d2 += vr[i] * vr[i];
        }
        #pragma unroll
        for (int off = 16; off > 0; off >>= 1) {
            d1 += __shfl_xor_sync(0xffffffffu, d1, off);
            d2 += __shfl_xor_sync(0xffffffffu, d2, off);
        }
        if (lane == 0) { sred[warp] = d1; sred[8 + warp] = d2; }
        __syncthreads();
        float t1 = 0.f, t2 = 0.f;
        #pragma unroll
        for (int w = 0; w < 8; w++) { t1 += sred[w]; t2 += sred[8 + w]; }
        float f = 2.f * t1 / (t2 + 1e-8f);
        #pragma unroll
        for (int i = 0; i < 4; i++) hv[i] -= f * vr[i];
        __syncthreads();  // before sred reuse
    }

    #pragma unroll
    for (int i = 0; i < 4; i++) hr[tid + 256 * i] = hv[i];
}

// ---------------------------------------------------------------------------
// Causal attention, online softmax. Warp-per-query-row, 8 rows/block,
// K/V staged through SMEM in chunks of 32 keys.
// Layout: Q/K/V/O are [B, S, H*DH] with head h at column offset h*128.
// ---------------------------------------------------------------------------
__global__ void attn_kernel(const float* __restrict__ Q,
                            const float* __restrict__ K,
                            const float* __restrict__ V,
                            float* __restrict__ O)
{
    const float scale = 0.08838834764831845f;  // 1/sqrt(128)
    int bh = blockIdx.y;
    int b = bh >> 3, hh = bh & 7;
    int q0 = blockIdx.x * 8;
    int tid = threadIdx.x, lane = tid & 31, warp = tid >> 5;

    const float* Qb = Q + (size_t)b * SEQ * DIM + hh * DHEAD;
    const float* Kb = K + (size_t)b * SEQ * DIM + hh * DHEAD;
    const float* Vb = V + (size_t)b * SEQ * DIM + hh * DHEAD;
    float*       Ob = O + (size_t)b * SEQ * DIM + hh * DHEAD;

    int qrow = q0 + warp;
    float q[4], acc[4] = {0.f, 0.f, 0.f, 0.f};
    #pragma unroll
    for (int i = 0; i < 4; i++) q[i] = Qb[(size_t)qrow * DIM + lane + 32 * i];

    float mi = -1e30f, li = 0.f;

    __shared__ float Ks[32][DHEAD];
    __shared__ float Vs[32][DHEAD];

    int kend = q0 + 8;   // need keys [0, kend)
    for (int c0 = 0; c0 < kend; c0 += 32) {
        __syncthreads();
        for (int idx = tid; idx < 32 * DHEAD; idx += 256) {
            int j = idx >> 7, d = idx & 127;
            Ks[j][d] = Kb[(size_t)(c0 + j) * DIM + d];
            Vs[j][d] = Vb[(size_t)(c0 + j) * DIM + d];
        }
        __syncthreads();

        int jend = min(32, kend - c0);
        for (int j = 0; j < jend; j++) {
            int kg = c0 + j;
            if (kg > qrow) break;   // causal (exp(-1e9-m)==0 in fp32 -> exact skip)
            float s = q[0] * Ks[j][lane]      + q[1] * Ks[j][lane + 32]
                    + q[2] * Ks[j][lane + 64] + q[3] * Ks[j][lane + 96];
            #pragma unroll
            for (int off = 16; off > 0; off >>= 1)
                s += __shfl_xor_sync(0xffffffffu, s, off);
            s *= scale;
            float mnew = fmaxf(mi, s);
            float corr = expf(mi - mnew);
            float p    = expf(s - mnew);
            li = li * corr + p;
            #pragma unroll
            for (int i = 0; i < 4; i++)
                acc[i] = acc[i] * corr + p * Vs[j][lane + 32 * i];
            mi = mnew;
        }
    }

    float inv = 1.f / li;
    #pragma unroll
    for (int i = 0; i < 4; i++)
        Ob[(size_t)qrow * DIM + lane + 32 * i] = acc[i] * inv;
}

// ---------------------------------------------------------------------------
// Launch
// ---------------------------------------------------------------------------
extern "C" void kernel_launch(void* const* d_in, const int* in_sizes, int n_in,
                              void* d_out, int out_size)
{
    const float* x       = (const float*)d_in[0];
    // d_in[1] = mask (ignored; causal handled analytically)
    const float* Wr_in   = (const float*)d_in[2];
    const float* Wr_proc = (const float*)d_in[3];
    const float* Wr_out  = (const float*)d_in[4];
    const float* WrO_in  = (const float*)d_in[5];
    const float* WrO_proc= (const float*)d_in[6];
    const float* WrO_out = (const float*)d_in[7];
    const float* Wq_in   = (const float*)d_in[8];
    const float* vq      = (const float*)d_in[9];
    const float* Wq_out  = (const float*)d_in[10];
    const float* Wk_in   = (const float*)d_in[11];
    const float* vk      = (const float*)d_in[12];
    const float* Wk_out  = (const float*)d_in[13];
    const float* Wv_in   = (const float*)d_in[14];
    const float* vv      = (const float*)d_in[15];
    const float* Wv_out  = (const float*)d_in[16];
    const float* Wo_in   = (const float*)d_in[17];
    const float* vo      = (const float*)d_in[18];
    const float* Wo_out  = (const float*)d_in[19];
    float* out = (float*)d_out;

    float *h, *Q, *Kc, *V, *O, *inw, *outw;
    int* pidx;
    cudaGetSymbolAddress((void**)&h,    g_h);
    cudaGetSymbolAddress((void**)&Q,    g_Q);
    cudaGetSymbolAddress((void**)&Kc,   g_Kc);
    cudaGetSymbolAddress((void**)&V,    g_V);
    cudaGetSymbolAddress((void**)&O,    g_O);
    cudaGetSymbolAddress((void**)&inw,  g_inw);
    cudaGetSymbolAddress((void**)&outw, g_outw);
    cudaGetSymbolAddress((void**)&pidx, g_pidx);

    dim3 gGemm(DIM / 128, TOK / 128);   // (8, 32)

    // Router on x
    router_kernel<<<TOK, 128>>>(x, Wr_in, Wr_proc, Wr_out, inw, pidx, outw);

    // Q circuit
    circuit_gemm_kernel<<<gGemm, 256>>>(x, Wq_in, inw, h);
    householder_kernel<<<TOK, 256>>>(h, vq, pidx);
    circuit_gemm_kernel<<<gGemm, 256>>>(h, Wq_out, outw, Q);

    // K circuit
    circuit_gemm_kernel<<<gGemm, 256>>>(x, Wk_in, inw, h);
    householder_kernel<<<TOK, 256>>>(h, vk, pidx);
    circuit_gemm_kernel<<<gGemm, 256>>>(h, Wk_out, outw, Kc);

    // V circuit
    circuit_gemm_kernel<<<gGemm, 256>>>(x, Wv_in, inw, h);
    householder_kernel<<<TOK, 256>>>(h, vv, pidx);
    circuit_gemm_kernel<<<gGemm, 256>>>(h, Wv_out, outw, V);

    // Attention
    attn_kernel<<<dim3(SEQ / 8, NBATCH * NH), 256>>>(Q, Kc, V, O);

    // Router on o + output circuit
    router_kernel<<<TOK, 128>>>(O, WrO_in, WrO_proc, WrO_out, inw, pidx, outw);
    circuit_gemm_kernel<<<gGemm, 256>>>(O, Wo_in, inw, h);
    householder_kernel<<<TOK, 256>>>(h, vo, pidx);
    circuit_gemm_kernel<<<gGemm, 256>>>(h, Wo_out, outw, out);

    (void)in_sizes; (void)n_in; (void)out_size;
}

// round 4
// speedup vs baseline: 1.5873x; 1.5873x over previous
#include <cuda_runtime.h>
#include <cuda_bf16.h>
#include <math.h>
#include <stdint.h>

// Problem constants
#define TOK   4096      // B*S
#define DIM   1024      // D == R
#define SEQ   2048
#define NBATCH 2
#define NH    8
#define DHEAD 128
#define NEXP  8
#define NPROC 32
#define TOPK  3
#define KTOT  8192      // NEXP * DIM

// GEMM tiling
#define BK      64
#define NCHUNK  (KTOT / BK)       // 128
#define PAD     72                // smem row stride in bf16 halves (144B)
#define MAT_BYTES   (128 * PAD * 2)   // 18432 per matrix
#define STAGE_BYTES (4 * MAT_BYTES)   // Ahi, Alo, Bhi, Blo
#define SMEM_GEMM_BYTES (2 * STAGE_BYTES)   // 147456

// ---------------------------------------------------------------------------
// Scratch (device globals — no runtime allocation allowed)
// ---------------------------------------------------------------------------
__device__ float g_h  [TOK * DIM];
__device__ float g_Q  [TOK * DIM];
__device__ float g_Kc [TOK * DIM];
__device__ float g_V  [TOK * DIM];
__device__ float g_O  [TOK * DIM];
__device__ float g_inw [TOK * NEXP];
__device__ float g_outw[TOK * NEXP];
__device__ int   g_pidx[TOK * TOPK];
__device__ __nv_bfloat16 g_whi[DIM * KTOT];   // transposed weight hi [N=1024, K=8192]
__device__ __nv_bfloat16 g_wlo[DIM * KTOT];   // transposed weight lo

// ---------------------------------------------------------------------------
// Portable tensor-core helpers (sm_80+ PTX; no 'a'-suffix features)
// ---------------------------------------------------------------------------
#define LDSM4(r0, r1, r2, r3, addr) \
    asm volatile("ldmatrix.sync.aligned.m8n8.x4.shared.b16 {%0,%1,%2,%3}, [%4];" \
                 : "=r"(r0), "=r"(r1), "=r"(r2), "=r"(r3) : "r"(addr))

__device__ __forceinline__ void mma_bf16(float* c, const uint32_t* a, const uint32_t* b) {
    asm volatile(
        "mma.sync.aligned.m16n8k16.row.col.f32.bf16.bf16.f32 "
        "{%0,%1,%2,%3}, {%4,%5,%6,%7}, {%8,%9}, {%0,%1,%2,%3};"
        : "+f"(c[0]), "+f"(c[1]), "+f"(c[2]), "+f"(c[3])
        : "r"(a[0]), "r"(a[1]), "r"(a[2]), "r"(a[3]), "r"(b[0]), "r"(b[1]));
}

__device__ __forceinline__ void cp16(uint32_t saddr, const void* gaddr) {
    asm volatile("cp.async.cg.shared.global [%0], [%1], 16;" :: "r"(saddr), "l"(gaddr));
}
__device__ __forceinline__ void cp_commit() {
    asm volatile("cp.async.commit_group;" ::: "memory");
}
__device__ __forceinline__ void cp_wait0() {
    asm volatile("cp.async.wait_group 0;" ::: "memory");
}

// ---------------------------------------------------------------------------
// Weight prep: W[KTOT, DIM] fp32 -> transposed bf16 hi/lo [DIM, KTOT]
// ---------------------------------------------------------------------------
__global__ void prep_w_kernel(const float* __restrict__ W,
                              __nv_bfloat16* __restrict__ Whi,
                              __nv_bfloat16* __restrict__ Wlo)
{
    __shared__ float ts[32][33];
    int k0 = blockIdx.y * 32, n0 = blockIdx.x * 32;
    int tx = threadIdx.x & 31, ty = threadIdx.x >> 5;   // 32 x 8
    #pragma unroll
    for (int r = 0; r < 4; r++) {
        int k = ty + r * 8;
        ts[k][tx] = W[(size_t)(k0 + k) * DIM + n0 + tx];
    }
    __syncthreads();
    #pragma unroll
    for (int r = 0; r < 4; r++) {
        int n = ty + r * 8;
        float v = ts[tx][n];                      // W[k0+tx][n0+n]
        __nv_bfloat16 h = __float2bfloat16_rn(v);
        float lo = v - __bfloat162float(h);
        size_t o = (size_t)(n0 + n) * KTOT + k0 + tx;
        Whi[o] = h;
        Wlo[o] = __float2bfloat16_rn(lo);
    }
}

// ---------------------------------------------------------------------------
// Tensor-core mixture GEMM via mma.sync (split-bf16, 3 passes, fp32 acc)
// out[t, n] = sum_{k<8192} (wgt[t, k>>10] * act[t, k&1023]) * W[k, n]
// ---------------------------------------------------------------------------
__global__ __launch_bounds__(256)
void circuit_gemm_tc(const float* __restrict__ act,
                     const __nv_bfloat16* __restrict__ Whi,  // [N, K]
                     const __nv_bfloat16* __restrict__ Wlo,
                     const float* __restrict__ wgt,          // [TOK, NEXP]
                     float* __restrict__ out)                // [TOK, DIM]
{
    extern __shared__ char smem[];
    const uint32_t sb = (uint32_t)__cvta_generic_to_shared(smem);
    int tid = threadIdx.x, lane = tid & 31, wid = tid >> 5;
    int bm = blockIdx.y * 128, bn = blockIdx.x * 128;

    // ---- loader role: thread pair per row, 32-k half each ----
    int r  = tid >> 1;
    int kh = (tid & 1) * 32;
    const float* actp = act + (size_t)(bm + r) * DIM;
    const float* wgtp = wgt + (size_t)(bm + r) * NEXP;
    const __nv_bfloat16* bhip = Whi + (size_t)(bn + r) * KTOT;
    const __nv_bfloat16* blop = Wlo + (size_t)(bn + r) * KTOT;
    const uint32_t rowoff = (uint32_t)(r * PAD + kh) * 2;   // byte offset in matrix

    auto load_chunk = [&](int c, int s) {
        uint32_t st = sb + (uint32_t)s * STAGE_BYTES;
        int k0 = c * BK;
        // B tiles straight to SMEM via cp.async (4x16B hi + 4x16B lo)
        #pragma unroll
        for (int ci = 0; ci < 4; ci++) {
            cp16(st + 2 * MAT_BYTES + rowoff + ci * 16, bhip + k0 + kh + ci * 8);
            cp16(st + 3 * MAT_BYTES + rowoff + ci * 16, blop + k0 + kh + ci * 8);
        }
        // A tile: fp32 -> scale -> bf16 hi/lo -> STS
        float scale = wgtp[k0 >> 10];
        int d0 = (k0 & (DIM - 1)) + kh;
        char* sm = smem + (size_t)s * STAGE_BYTES;
        #pragma unroll
        for (int ci = 0; ci < 4; ci++) {
            float4 a0 = *(const float4*)(actp + d0 + ci * 8);
            float4 a1 = *(const float4*)(actp + d0 + ci * 8 + 4);
            float v[8] = { a0.x * scale, a0.y * scale, a0.z * scale, a0.w * scale,
                           a1.x * scale, a1.y * scale, a1.z * scale, a1.w * scale };
            uint4 hq, lq;
            uint32_t* hp = (uint32_t*)&hq;
            uint32_t* lp = (uint32_t*)&lq;
            #pragma unroll
            for (int j = 0; j < 4; j++) {
                __nv_bfloat162 hh = __floats2bfloat162_rn(v[2*j], v[2*j+1]);
                uint32_t hb = *(uint32_t*)&hh;
                float h0 = __uint_as_float(hb << 16);
                float h1 = __uint_as_float(hb & 0xFFFF0000u);
                __nv_bfloat162 ll = __floats2bfloat162_rn(v[2*j] - h0, v[2*j+1] - h1);
                hp[j] = hb;
                lp[j] = *(uint32_t*)&ll;
            }
            *(uint4*)(sm + rowoff + ci * 16)             = hq;   // Ahi
            *(uint4*)(sm + MAT_BYTES + rowoff + ci * 16) = lq;   // Alo
        }
        cp_commit();
    };

    // ---- compute role: 2(M) x 4(N) warp grid, 64x32 warp tile ----
    int wm = (wid >> 2) * 64;
    int wn = (wid & 3) * 32;
    int arow = lane & 15;
    int acol = (lane >> 4) * 8;
    int q    = lane >> 3, rl = lane & 7;
    int brow = wn + ((q >= 2) ? 8 : 0) + rl;
    int bcol = (q & 1) * 8;
    const uint32_t aOffHi = (uint32_t)((wm + arow) * PAD + acol) * 2;
    const uint32_t bOffHi = (uint32_t)(2 * MAT_BYTES) + (uint32_t)(brow * PAD + bcol) * 2;

    float acc[4][4][4];
    #pragma unroll
    for (int i = 0; i < 4; i++)
        #pragma unroll
        for (int j = 0; j < 4; j++)
            #pragma unroll
            for (int e = 0; e < 4; e++) acc[i][j][e] = 0.f;

    // ---- mainloop ----
    load_chunk(0, 0);
    cp_wait0();
    __syncthreads();

    #pragma unroll 1
    for (int c = 0; c < NCHUNK; c++) {
        int cur = c & 1;
        if (c + 1 < NCHUNK) load_chunk(c + 1, cur ^ 1);

        uint32_t st = sb + (uint32_t)cur * STAGE_BYTES;
        uint32_t aHi = st + aOffHi;
        uint32_t bHi = st + bOffHi;

        #pragma unroll
        for (int ks = 0; ks < 4; ks++) {
            uint32_t kb = (uint32_t)(ks * 16) * 2;
            uint32_t bh[4][2], bl[4][2];
            #pragma unroll
            for (int p = 0; p < 2; p++) {
                uint32_t ba = bHi + (uint32_t)(p * 16 * PAD) * 2 + kb;
                LDSM4(bh[2*p][0], bh[2*p][1], bh[2*p+1][0], bh[2*p+1][1], ba);
                LDSM4(bl[2*p][0], bl[2*p][1], bl[2*p+1][0], bl[2*p+1][1], ba + MAT_BYTES);
            }
            #pragma unroll
            for (int mt = 0; mt < 4; mt++) {
                uint32_t aa = aHi + (uint32_t)(mt * 16 * PAD) * 2 + kb;
                uint32_t ah[4], al[4];
                LDSM4(ah[0], ah[1], ah[2], ah[3], aa);
                LDSM4(al[0], al[1], al[2], al[3], aa + MAT_BYTES);
                #pragma unroll
                for (int nt = 0; nt < 4; nt++) {
                    mma_bf16(acc[mt][nt], ah, bh[nt]);
                    mma_bf16(acc[mt][nt], ah, bl[nt]);
                    mma_bf16(acc[mt][nt], al, bh[nt]);
                }
            }
        }

        if (c + 1 < NCHUNK) cp_wait0();
        __syncthreads();
    }

    // ---- epilogue ----
    int g = lane >> 2, tig = lane & 3;
    #pragma unroll
    for (int mt = 0; mt < 4; mt++) {
        #pragma unroll
        for (int nt = 0; nt < 4; nt++) {
            int row = bm + wm + mt * 16 + g;
            int col = bn + wn + nt * 8 + tig * 2;
            *(float2*)(out + (size_t)row * DIM + col) =
                make_float2(acc[mt][nt][0], acc[mt][nt][1]);
            *(float2*)(out + (size_t)(row + 8) * DIM + col) =
                make_float2(acc[mt][nt][2], acc[mt][nt][3]);
        }
    }
}

// ---------------------------------------------------------------------------
// Router: 48 logits per token (8 in / 32 proc / 8 out), softmax8 x2 + top-3
// ---------------------------------------------------------------------------
__global__ void router_kernel(const float* __restrict__ act,
                              const float* __restrict__ Wi,
                              const float* __restrict__ Wp,
                              const float* __restrict__ Wo,
                              float* __restrict__ inw,
                              int*   __restrict__ pidx,
                              float* __restrict__ outw)
{
    int t    = blockIdx.x;
    int tid  = threadIdx.x;
    int lane = tid & 31, warp = tid >> 5;
    __shared__ float xs[DIM];
    __shared__ float lg[48];

    const float* xr = act + (size_t)t * DIM;
    for (int i = tid; i < DIM; i += 128) xs[i] = xr[i];
    __syncthreads();

    for (int l = warp; l < 48; l += 4) {
        const float* wr = (l < 8) ? (Wi + (size_t)l * DIM)
                        : (l < 40) ? (Wp + (size_t)(l - 8) * DIM)
                                   : (Wo + (size_t)(l - 40) * DIM);
        float s = 0.f;
        for (int d = lane; d < DIM; d += 32) s += xs[d] * wr[d];
        #pragma unroll
        for (int off = 16; off > 0; off >>= 1)
            s += __shfl_xor_sync(0xffffffffu, s, off);
        if (lane == 0) lg[l] = s;
    }
    __syncthreads();

    if (tid == 0) {
        float m = lg[0];
        for (int i = 1; i < 8; i++) m = fmaxf(m, lg[i]);
        float e[8], sum = 0.f;
        for (int i = 0; i < 8; i++) { e[i] = expf(lg[i] - m); sum += e[i]; }
        for (int i = 0; i < 8; i++) inw[t * 8 + i] = e[i] / sum;

        bool used[NPROC];
        for (int n = 0; n < NPROC; n++) used[n] = false;
        for (int r = 0; r < TOPK; r++) {
            float best = -INFINITY; int bi = 0;
            for (int n = 0; n < NPROC; n++)
                if (!used[n] && lg[8 + n] > best) { best = lg[8 + n]; bi = n; }
            used[bi] = true;
            pidx[t * TOPK + r] = bi;
        }

        m = lg[40];
        for (int i = 1; i < 8; i++) m = fmaxf(m, lg[40 + i]);
        sum = 0.f;
        for (int i = 0; i < 8; i++) { e[i] = expf(lg[40 + i] - m); sum += e[i]; }
        for (int i = 0; i < 8; i++) outw[t * 8 + i] = e[i] / sum;
    }
}

// ---------------------------------------------------------------------------
// Householder reflections: h -= 2 (h.v)/(v.v + 1e-8) v, 3x per token
// ---------------------------------------------------------------------------
__global__ void householder_kernel(float* __restrict__ hbuf,
                                   const float* __restrict__ vproc,
                                   const int* __restrict__ pidx)
{
    int t = blockIdx.x, tid = threadIdx.x;
    int lane = tid & 31, warp = tid >> 5;
    float* hr = hbuf + (size_t)t * DIM;

    float hv[4];
    #pragma unroll
    for (int i = 0; i < 4; i++) hv[i] = hr[tid + 256 * i];

    __shared__ float sred[16];

    for (int rfl = 0; rfl < TOPK; rfl++) {
        int idx = pidx[t * TOPK + rfl];
        const float* v = vproc + (size_t)idx * DIM;
        float vr[4];
        float d1 = 0.f, d2 = 0.f;
        #pragma unroll
        for (int i = 0; i < 4; i++) {
            vr[i] = v[tid + 256 * i];
            d1 += hv[i] * vr[i];
            d2 += vr[i] * vr[i];
        }
        #pragma unroll
        for (int off = 16; off > 0; off >>= 1) {
            d1 += __shfl_xor_sync(0xffffffffu, d1, off);
            d2 += __shfl_xor_sync(0xffffffffu, d2, off);
        }
        if (lane == 0) { sred[warp] = d1; sred[8 + warp] = d2; }
        __syncthreads();
        float t1 = 0.f, t2 = 0.f;
        #pragma unroll
        for (int w = 0; w < 8; w++) { t1 += sred[w]; t2 += sred[8 + w]; }
        float f = 2.f * t1 / (t2 + 1e-8f);
        #pragma unroll
        for (int i = 0; i < 4; i++) hv[i] -= f * vr[i];
        __syncthreads();
    }

    #pragma unroll
    for (int i = 0; i < 4; i++) hr[tid + 256 * i] = hv[i];
}

// ---------------------------------------------------------------------------
// Causal attention, online softmax (fp32), warp-per-query-row
// ---------------------------------------------------------------------------
__global__ void attn_kernel(const float* __restrict__ Q,
                            const float* __restrict__ K,
                            const float* __restrict__ V,
                            float* __restrict__ O)
{
    const float scale = 0.08838834764831845f;  // 1/sqrt(128)
    int bh = blockIdx.y;
    int b = bh >> 3, hh = bh & 7;
    int q0 = blockIdx.x * 8;
    int tid = threadIdx.x, lane = tid & 31, warp = tid >> 5;

    const float* Qb = Q + (size_t)b * SEQ * DIM + hh * DHEAD;
    const float* Kb = K + (size_t)b * SEQ * DIM + hh * DHEAD;
    const float* Vb = V + (size_t)b * SEQ * DIM + hh * DHEAD;
    float*       Ob = O + (size_t)b * SEQ * DIM + hh * DHEAD;

    int qrow = q0 + warp;
    float q[4], acc[4] = {0.f, 0.f, 0.f, 0.f};
    #pragma unroll
    for (int i = 0; i < 4; i++) q[i] = Qb[(size_t)qrow * DIM + lane + 32 * i];

    float mi = -1e30f, li = 0.f;

    __shared__ float Ks[32][DHEAD];
    __shared__ float Vs[32][DHEAD];

    int kend = q0 + 8;
    for (int c0 = 0; c0 < kend; c0 += 32) {
        __syncthreads();
        for (int idx = tid; idx < 32 * DHEAD; idx += 256) {
            int j = idx >> 7, d = idx & 127;
            Ks[j][d] = Kb[(size_t)(c0 + j) * DIM + d];
            Vs[j][d] = Vb[(size_t)(c0 + j) * DIM + d];
        }
        __syncthreads();

        int jend = min(32, kend - c0);
        for (int j = 0; j < jend; j++) {
            int kg = c0 + j;
            if (kg > qrow) break;
            float s = q[0] * Ks[j][lane]      + q[1] * Ks[j][lane + 32]
                    + q[2] * Ks[j][lane + 64] + q[3] * Ks[j][lane + 96];
            #pragma unroll
            for (int off = 16; off > 0; off >>= 1)
                s += __shfl_xor_sync(0xffffffffu, s, off);
            s *= scale;
            float mnew = fmaxf(mi, s);
            float corr = expf(mi - mnew);
            float p    = expf(s - mnew);
            li = li * corr + p;
            #pragma unroll
            for (int i = 0; i < 4; i++)
                acc[i] = acc[i] * corr + p * Vs[j][lane + 32 * i];
            mi = mnew;
        }
    }

    float inv = 1.f / li;
    #pragma unroll
    for (int i = 0; i < 4; i++)
        Ob[(size_t)qrow * DIM + lane + 32 * i] = acc[i] * inv;
}

// ---------------------------------------------------------------------------
// Launch
// ---------------------------------------------------------------------------
extern "C" void kernel_launch(void* const* d_in, const int* in_sizes, int n_in,
                              void* d_out, int out_size)
{
    const float* x       = (const float*)d_in[0];
    const float* Wr_in   = (const float*)d_in[2];
    const float* Wr_proc = (const float*)d_in[3];
    const float* Wr_out  = (const float*)d_in[4];
    const float* WrO_in  = (const float*)d_in[5];
    const float* WrO_proc= (const float*)d_in[6];
    const float* WrO_out = (const float*)d_in[7];
    const float* Wq_in   = (const float*)d_in[8];
    const float* vq      = (const float*)d_in[9];
    const float* Wq_out  = (const float*)d_in[10];
    const float* Wk_in   = (const float*)d_in[11];
    const float* vk      = (const float*)d_in[12];
    const float* Wk_out  = (const float*)d_in[13];
    const float* Wv_in   = (const float*)d_in[14];
    const float* vv      = (const float*)d_in[15];
    const float* Wv_out  = (const float*)d_in[16];
    const float* Wo_in   = (const float*)d_in[17];
    const float* vo      = (const float*)d_in[18];
    const float* Wo_out  = (const float*)d_in[19];
    float* out = (float*)d_out;

    float *h, *Q, *Kc, *V, *O, *inw, *outw;
    int* pidx;
    __nv_bfloat16 *whi, *wlo;
    cudaGetSymbolAddress((void**)&h,    g_h);
    cudaGetSymbolAddress((void**)&Q,    g_Q);
    cudaGetSymbolAddress((void**)&Kc,   g_Kc);
    cudaGetSymbolAddress((void**)&V,    g_V);
    cudaGetSymbolAddress((void**)&O,    g_O);
    cudaGetSymbolAddress((void**)&inw,  g_inw);
    cudaGetSymbolAddress((void**)&outw, g_outw);
    cudaGetSymbolAddress((void**)&pidx, g_pidx);
    cudaGetSymbolAddress((void**)&whi,  g_whi);
    cudaGetSymbolAddress((void**)&wlo,  g_wlo);

    cudaFuncSetAttribute(circuit_gemm_tc,
                         cudaFuncAttributeMaxDynamicSharedMemorySize,
                         SMEM_GEMM_BYTES);

    dim3 gGemm(DIM / 128, TOK / 128);     // (8, 32)
    dim3 gPrep(DIM / 32, KTOT / 32);      // (32, 256)

    auto gemm = [&](const float* a, const float* W, const float* wg, float* o) {
        prep_w_kernel<<<gPrep, 256>>>(W, whi, wlo);
        circuit_gemm_tc<<<gGemm, 256, SMEM_GEMM_BYTES>>>(a, whi, wlo, wg, o);
    };

    // Router on x
    router_kernel<<<TOK, 128>>>(x, Wr_in, Wr_proc, Wr_out, inw, pidx, outw);

    // Q circuit
    gemm(x, Wq_in, inw, h);
    householder_kernel<<<TOK, 256>>>(h, vq, pidx);
    gemm(h, Wq_out, outw, Q);

    // K circuit
    gemm(x, Wk_in, inw, h);
    householder_kernel<<<TOK, 256>>>(h, vk, pidx);
    gemm(h, Wk_out, outw, Kc);

    // V circuit
    gemm(x, Wv_in, inw, h);
    householder_kernel<<<TOK, 256>>>(h, vv, pidx);
    gemm(h, Wv_out, outw, V);

    // Attention
    attn_kernel<<<dim3(SEQ / 8, NBATCH * NH), 256>>>(Q, Kc, V, O);

    // Router on o + output circuit
    router_kernel<<<TOK, 128>>>(O, WrO_in, WrO_proc, WrO_out, inw, pidx, outw);
    gemm(O, Wo_in, inw, h);
    householder_kernel<<<TOK, 256>>>(h, vo, pidx);
    gemm(h, Wo_out, outw, out);

    (void)in_sizes; (void)n_in; (void)out_size;
}

// round 5
// speedup vs baseline: 1.7422x; 1.0976x over previous
#include <cuda_runtime.h>
#include <cuda_bf16.h>
#include <math.h>
#include <stdint.h>

// Problem constants
#define TOK   4096      // B*S
#define DIM   1024      // D == R
#define SEQ   2048
#define NBATCH 2
#define NH    8
#define DHEAD 128
#define NEXP  8
#define NPROC 32
#define TOPK  3
#define KTOT  8192      // NEXP * DIM

// GEMM tiling
#define BK      64
#define NCHUNK  (KTOT / BK)           // 128
#define PAD     72                    // smem row stride in bf16 halves
#define MAT_BYTES   (128 * PAD * 2)   // 18432 per matrix
#define STAGE_BYTES (4 * MAT_BYTES)   // Ahi, Alo, Bhi, Blo
#define NSTAGE  3
#define SMEM_GEMM_BYTES (NSTAGE * STAGE_BYTES)   // 221184

// ---------------------------------------------------------------------------
// Scratch (device globals — no runtime allocation allowed)
// ---------------------------------------------------------------------------
__device__ float g_h  [TOK * DIM];
__device__ float g_Q  [TOK * DIM];
__device__ float g_Kc [TOK * DIM];
__device__ float g_V  [TOK * DIM];
__device__ float g_O  [TOK * DIM];
__device__ float g_inw [TOK * NEXP];
__device__ float g_outw[TOK * NEXP];
__device__ int   g_pidx[TOK * TOPK];
__device__ __nv_bfloat16 g_whi[DIM * KTOT];   // weightT hi [N=1024, K=8192]
__device__ __nv_bfloat16 g_wlo[DIM * KTOT];
__device__ __nv_bfloat16 g_xhi[TOK * DIM];    // activation split (x / O)
__device__ __nv_bfloat16 g_xlo[TOK * DIM];
__device__ __nv_bfloat16 g_hhi[TOK * DIM];    // householder output split
__device__ __nv_bfloat16 g_hlo[TOK * DIM];

// ---------------------------------------------------------------------------
// Portable tensor-core helpers (sm_80+ PTX; no 'a'-suffix features)
// ---------------------------------------------------------------------------
#define LDSM4(r0, r1, r2, r3, addr) \
    asm volatile("ldmatrix.sync.aligned.m8n8.x4.shared.b16 {%0,%1,%2,%3}, [%4];" \
                 : "=r"(r0), "=r"(r1), "=r"(r2), "=r"(r3) : "r"(addr))

__device__ __forceinline__ void mma_bf16(float* c, const uint32_t* a, const uint32_t* b) {
    asm volatile(
        "mma.sync.aligned.m16n8k16.row.col.f32.bf16.bf16.f32 "
        "{%0,%1,%2,%3}, {%4,%5,%6,%7}, {%8,%9}, {%0,%1,%2,%3};"
        : "+f"(c[0]), "+f"(c[1]), "+f"(c[2]), "+f"(c[3])
        : "r"(a[0]), "r"(a[1]), "r"(a[2]), "r"(a[3]), "r"(b[0]), "r"(b[1]));
}

__device__ __forceinline__ void cp16(uint32_t saddr, const void* gaddr) {
    asm volatile("cp.async.cg.shared.global [%0], [%1], 16;" :: "r"(saddr), "l"(gaddr));
}
__device__ __forceinline__ void cp_commit() {
    asm volatile("cp.async.commit_group;" ::: "memory");
}
template <int N>
__device__ __forceinline__ void cp_wait() {
    asm volatile("cp.async.wait_group %0;" :: "n"(N) : "memory");
}

__device__ __forceinline__ void split_bf16(float v, __nv_bfloat16& hi, __nv_bfloat16& lo) {
    hi = __float2bfloat16_rn(v);
    lo = __float2bfloat16_rn(v - __bfloat162float(hi));
}

// ---------------------------------------------------------------------------
// Weight prep: W[KTOT, DIM] fp32 -> transposed bf16 hi/lo [DIM, KTOT]
// ---------------------------------------------------------------------------
__global__ void prep_w_kernel(const float* __restrict__ W,
                              __nv_bfloat16* __restrict__ Whi,
                              __nv_bfloat16* __restrict__ Wlo)
{
    __shared__ float ts[32][33];
    int k0 = blockIdx.y * 32, n0 = blockIdx.x * 32;
    int tx = threadIdx.x & 31, ty = threadIdx.x >> 5;   // 32 x 8
    #pragma unroll
    for (int r = 0; r < 4; r++) {
        int k = ty + r * 8;
        ts[k][tx] = W[(size_t)(k0 + k) * DIM + n0 + tx];
    }
    __syncthreads();
    #pragma unroll
    for (int r = 0; r < 4; r++) {
        int n = ty + r * 8;
        float v = ts[tx][n];                      // W[k0+tx][n0+n]
        __nv_bfloat16 h, l;
        split_bf16(v, h, l);
        size_t o = (size_t)(n0 + n) * KTOT + k0 + tx;
        Whi[o] = h;
        Wlo[o] = l;
    }
}

// ---------------------------------------------------------------------------
// Activation split: fp32 [TOK,DIM] -> bf16 hi/lo
// ---------------------------------------------------------------------------
__global__ void split_kernel(const float* __restrict__ src,
                             __nv_bfloat16* __restrict__ hi,
                             __nv_bfloat16* __restrict__ lo)
{
    int i = (blockIdx.x * 256 + threadIdx.x) * 4;
    float4 v = *(const float4*)(src + i);
    __nv_bfloat16 h[4], l[4];
    split_bf16(v.x, h[0], l[0]);
    split_bf16(v.y, h[1], l[1]);
    split_bf16(v.z, h[2], l[2]);
    split_bf16(v.w, h[3], l[3]);
    *(uint64_t*)(hi + i) = *(uint64_t*)h;
    *(uint64_t*)(lo + i) = *(uint64_t*)l;
}

// ---------------------------------------------------------------------------
// Tensor-core mixture GEMM via mma.sync (split-bf16, 3 passes, fp32 acc).
// A = unscaled split activation [TOK, DIM] (columns cycle mod 1024);
// expert scale w[t,e] applied in registers at expert-segment boundaries.
// ---------------------------------------------------------------------------
__global__ __launch_bounds__(256)
void circuit_gemm_tc(const __nv_bfloat16* __restrict__ Ahi,  // [TOK, DIM]
                     const __nv_bfloat16* __restrict__ Alo,
                     const __nv_bfloat16* __restrict__ Whi,  // [N, K]
                     const __nv_bfloat16* __restrict__ Wlo,
                     const float* __restrict__ wgt,          // [TOK, NEXP]
                     float* __restrict__ out)                // [TOK, DIM]
{
    extern __shared__ char smem[];
    __shared__ float swgt[128 * NEXP];
    const uint32_t sb = (uint32_t)__cvta_generic_to_shared(smem);
    int tid = threadIdx.x, lane = tid & 31, wid = tid >> 5;
    int bm = blockIdx.y * 128, bn = blockIdx.x * 128;

    // ---- loader role: thread pair per row, 32-k half each ----
    int r  = tid >> 1;
    int kh = (tid & 1) * 32;
    const __nv_bfloat16* ahip = Ahi + (size_t)(bm + r) * DIM + kh;
    const __nv_bfloat16* alop = Alo + (size_t)(bm + r) * DIM + kh;
    const __nv_bfloat16* bhip = Whi + (size_t)(bn + r) * KTOT + kh;
    const __nv_bfloat16* blop = Wlo + (size_t)(bn + r) * KTOT + kh;
    const uint32_t rowoff = (uint32_t)(r * PAD + kh) * 2;

    auto load_chunk = [&](int c) {
        uint32_t st = sb + (uint32_t)(c % NSTAGE) * STAGE_BYTES;
        int k0 = c * BK;
        int d0 = k0 & (DIM - 1);
        #pragma unroll
        for (int ci = 0; ci < 4; ci++) {
            cp16(st + rowoff + ci * 16,                 ahip + d0 + ci * 8);
            cp16(st + MAT_BYTES + rowoff + ci * 16,     alop + d0 + ci * 8);
            cp16(st + 2 * MAT_BYTES + rowoff + ci * 16, bhip + k0 + ci * 8);
            cp16(st + 3 * MAT_BYTES + rowoff + ci * 16, blop + k0 + ci * 8);
        }
        cp_commit();
    };

    // ---- compute role: 2(M) x 4(N) warp grid, 64x32 warp tile ----
    int wm = (wid >> 2) * 64;
    int wn = (wid & 3) * 32;
    int arow = lane & 15;
    int acol = (lane >> 4) * 8;
    int q    = lane >> 3, rl = lane & 7;
    int brow = wn + ((q >= 2) ? 8 : 0) + rl;
    int bcol = (q & 1) * 8;
    const uint32_t aOff = (uint32_t)((wm + arow) * PAD + acol) * 2;
    const uint32_t bOff = (uint32_t)(2 * MAT_BYTES) + (uint32_t)(brow * PAD + bcol) * 2;
    int g = lane >> 2;

    float acc[4][4][4];
    float seg[4][4][4];
    #pragma unroll
    for (int i = 0; i < 4; i++)
        #pragma unroll
        for (int j = 0; j < 4; j++)
            #pragma unroll
            for (int e = 0; e < 4; e++) acc[i][j][e] = 0.f;

    // ---- prologue ----
    for (int idx = tid; idx < 128 * NEXP; idx += 256)
        swgt[idx] = wgt[(size_t)(bm + (idx >> 3)) * NEXP + (idx & 7)];
    load_chunk(0);
    load_chunk(1);

    int c = 0;
    for (int e = 0; e < NEXP; e++) {
        #pragma unroll
        for (int i = 0; i < 4; i++)
            #pragma unroll
            for (int j = 0; j < 4; j++)
                #pragma unroll
                for (int t = 0; t < 4; t++) seg[i][j][t] = 0.f;

        for (int dc = 0; dc < 16; dc++, c++) {
            // own chunk-c copies retired
            if (c + 1 < NCHUNK) cp_wait<1>(); else cp_wait<0>();
            // all warps: done with stage (c-1)%3 compute + chunk-c data visible
            __syncthreads();
            if (c + 2 < NCHUNK) load_chunk(c + 2);

            uint32_t st = sb + (uint32_t)(c % NSTAGE) * STAGE_BYTES;
            uint32_t aHi = st + aOff;
            uint32_t bHi = st + bOff;

            #pragma unroll
            for (int ks = 0; ks < 4; ks++) {
                uint32_t kb = (uint32_t)(ks * 16) * 2;
                uint32_t bh[4][2], bl[4][2];
                #pragma unroll
                for (int p = 0; p < 2; p++) {
                    uint32_t ba = bHi + (uint32_t)(p * 16 * PAD) * 2 + kb;
                    LDSM4(bh[2*p][0], bh[2*p][1], bh[2*p+1][0], bh[2*p+1][1], ba);
                    LDSM4(bl[2*p][0], bl[2*p][1], bl[2*p+1][0], bl[2*p+1][1], ba + MAT_BYTES);
                }
                #pragma unroll
                for (int mt = 0; mt < 4; mt++) {
                    uint32_t aa = aHi + (uint32_t)(mt * 16 * PAD) * 2 + kb;
                    uint32_t ah[4], al[4];
                    LDSM4(ah[0], ah[1], ah[2], ah[3], aa);
                    LDSM4(al[0], al[1], al[2], al[3], aa + MAT_BYTES);
                    #pragma unroll
                    for (int nt = 0; nt < 4; nt++) {
                        mma_bf16(seg[mt][nt], ah, bh[nt]);
                        mma_bf16(seg[mt][nt], ah, bl[nt]);
                        mma_bf16(seg[mt][nt], al, bh[nt]);
                    }
                }
            }
        }

        // ---- expert boundary: acc += w(row, e) * seg ----
        #pragma unroll
        for (int mt = 0; mt < 4; mt++) {
            float w0 = swgt[(wm + mt * 16 + g) * NEXP + e];
            float w1 = swgt[(wm + mt * 16 + 8 + g) * NEXP + e];
            #pragma unroll
            for (int nt = 0; nt < 4; nt++) {
                acc[mt][nt][0] += w0 * seg[mt][nt][0];
                acc[mt][nt][1] += w0 * seg[mt][nt][1];
                acc[mt][nt][2] += w1 * seg[mt][nt][2];
                acc[mt][nt][3] += w1 * seg[mt][nt][3];
            }
        }
    }

    // ---- epilogue ----
    int tig = lane & 3;
    #pragma unroll
    for (int mt = 0; mt < 4; mt++) {
        #pragma unroll
        for (int nt = 0; nt < 4; nt++) {
            int row = bm + wm + mt * 16 + g;
            int col = bn + wn + nt * 8 + tig * 2;
            *(float2*)(out + (size_t)row * DIM + col) =
                make_float2(acc[mt][nt][0], acc[mt][nt][1]);
            *(float2*)(out + (size_t)(row + 8) * DIM + col) =
                make_float2(acc[mt][nt][2], acc[mt][nt][3]);
        }
    }
}

// ---------------------------------------------------------------------------
// Router: 48 logits per token (8 in / 32 proc / 8 out), softmax8 x2 + top-3
// ---------------------------------------------------------------------------
__global__ void router_kernel(const float* __restrict__ act,
                              const float* __restrict__ Wi,
                              const float* __restrict__ Wp,
                              const float* __restrict__ Wo,
                              float* __restrict__ inw,
                              int*   __restrict__ pidx,
                              float* __restrict__ outw)
{
    int t    = blockIdx.x;
    int tid  = threadIdx.x;
    int lane = tid & 31, warp = tid >> 5;
    __shared__ float xs[DIM];
    __shared__ float lg[48];

    const float* xr = act + (size_t)t * DIM;
    for (int i = tid; i < DIM; i += 128) xs[i] = xr[i];
    __syncthreads();

    for (int l = warp; l < 48; l += 4) {
        const float* wr = (l < 8) ? (Wi + (size_t)l * DIM)
                        : (l < 40) ? (Wp + (size_t)(l - 8) * DIM)
                                   : (Wo + (size_t)(l - 40) * DIM);
        float s = 0.f;
        for (int d = lane; d < DIM; d += 32) s += xs[d] * wr[d];
        #pragma unroll
        for (int off = 16; off > 0; off >>= 1)
            s += __shfl_xor_sync(0xffffffffu, s, off);
        if (lane == 0) lg[l] = s;
    }
    __syncthreads();

    if (tid == 0) {
        float m = lg[0];
        for (int i = 1; i < 8; i++) m = fmaxf(m, lg[i]);
        float e[8], sum = 0.f;
        for (int i = 0; i < 8; i++) { e[i] = expf(lg[i] - m); sum += e[i]; }
        for (int i = 0; i < 8; i++) inw[t * 8 + i] = e[i] / sum;

        bool used[NPROC];
        for (int n = 0; n < NPROC; n++) used[n] = false;
        for (int r = 0; r < TOPK; r++) {
            float best = -INFINITY; int bi = 0;
            for (int n = 0; n < NPROC; n++)
                if (!used[n] && lg[8 + n] > best) { best = lg[8 + n]; bi = n; }
            used[bi] = true;
            pidx[t * TOPK + r] = bi;
        }

        m = lg[40];
        for (int i = 1; i < 8; i++) m = fmaxf(m, lg[40 + i]);
        sum = 0.f;
        for (int i = 0; i < 8; i++) { e[i] = expf(lg[40 + i] - m); sum += e[i]; }
        for (int i = 0; i < 8; i++) outw[t * 8 + i] = e[i] / sum;
    }
}

// ---------------------------------------------------------------------------
// Householder reflections: h -= 2 (h.v)/(v.v + 1e-8) v, 3x per token;
// writes split bf16 hi/lo output (consumed only by the out-proj GEMM).
// ---------------------------------------------------------------------------
__global__ void householder_kernel(const float* __restrict__ hbuf,
                                   const float* __restrict__ vproc,
                                   const int* __restrict__ pidx,
                                   __nv_bfloat16* __restrict__ ohi,
                                   __nv_bfloat16* __restrict__ olo)
{
    int t = blockIdx.x, tid = threadIdx.x;
    int lane = tid & 31, warp = tid >> 5;
    const float* hr = hbuf + (size_t)t * DIM;

    float hv[4];
    #pragma unroll
    for (int i = 0; i < 4; i++) hv[i] = hr[tid + 256 * i];

    __shared__ float sred[16];

    for (int rfl = 0; rfl < TOPK; rfl++) {
        int idx = pidx[t * TOPK + rfl];
        const float* v = vproc + (size_t)idx * DIM;
        float vr[4];
        float d1 = 0.f, d2 = 0.f;
        #pragma unroll
        for (int i = 0; i < 4; i++) {
            vr[i] = v[tid + 256 * i];
            d1 += hv[i] * vr[i];
            d2 += vr[i] * vr[i];
        }
        #pragma unroll
        for (int off = 16; off > 0; off >>= 1) {
            d1 += __shfl_xor_sync(0xffffffffu, d1, off);
            d2 += __shfl_xor_sync(0xffffffffu, d2, off);
        }
        if (lane == 0) { sred[warp] = d1; sred[8 + warp] = d2; }
        __syncthreads();
        float t1 = 0.f, t2 = 0.f;
        #pragma unroll
        for (int w = 0; w < 8; w++) { t1 += sred[w]; t2 += sred[8 + w]; }
        float f = 2.f * t1 / (t2 + 1e-8f);
        #pragma unroll
        for (int i = 0; i < 4; i++) hv[i] -= f * vr[i];
        __syncthreads();
    }

    #pragma unroll
    for (int i = 0; i < 4; i++) {
        __nv_bfloat16 h, l;
        split_bf16(hv[i], h, l);
        ohi[(size_t)t * DIM + tid + 256 * i] = h;
        olo[(size_t)t * DIM + tid + 256 * i] = l;
    }
}

// ---------------------------------------------------------------------------
// Causal attention, online softmax (fp32), warp-per-query-row
// ---------------------------------------------------------------------------
__global__ void attn_kernel(const float* __restrict__ Q,
                            const float* __restrict__ K,
                            const float* __restrict__ V,
                            float* __restrict__ O)
{
    const float scale = 0.08838834764831845f;  // 1/sqrt(128)
    int bh = blockIdx.y;
    int b = bh >> 3, hh = bh & 7;
    int q0 = blockIdx.x * 8;
    int tid = threadIdx.x, lane = tid & 31, warp = tid >> 5;

    const float* Qb = Q + (size_t)b * SEQ * DIM + hh * DHEAD;
    const float* Kb = K + (size_t)b * SEQ * DIM + hh * DHEAD;
    const float* Vb = V + (size_t)b * SEQ * DIM + hh * DHEAD;
    float*       Ob = O + (size_t)b * SEQ * DIM + hh * DHEAD;

    int qrow = q0 + warp;
    float q[4], acc[4] = {0.f, 0.f, 0.f, 0.f};
    #pragma unroll
    for (int i = 0; i < 4; i++) q[i] = Qb[(size_t)qrow * DIM + lane + 32 * i];

    float mi = -1e30f, li = 0.f;

    __shared__ float Ks[32][DHEAD];
    __shared__ float Vs[32][DHEAD];

    int kend = q0 + 8;
    for (int c0 = 0; c0 < kend; c0 += 32) {
        __syncthreads();
        for (int idx = tid; idx < 32 * DHEAD; idx += 256) {
            int j = idx >> 7, d = idx & 127;
            Ks[j][d] = Kb[(size_t)(c0 + j) * DIM + d];
            Vs[j][d] = Vb[(size_t)(c0 + j) * DIM + d];
        }
        __syncthreads();

        int jend = min(32, kend - c0);
        for (int j = 0; j < jend; j++) {
            int kg = c0 + j;
            if (kg > qrow) break;
            float s = q[0] * Ks[j][lane]      + q[1] * Ks[j][lane + 32]
                    + q[2] * Ks[j][lane + 64] + q[3] * Ks[j][lane + 96];
            #pragma unroll
            for (int off = 16; off > 0; off >>= 1)
                s += __shfl_xor_sync(0xffffffffu, s, off);
            s *= scale;
            float mnew = fmaxf(mi, s);
            float corr = expf(mi - mnew);
            float p    = expf(s - mnew);
            li = li * corr + p;
            #pragma unroll
            for (int i = 0; i < 4; i++)
                acc[i] = acc[i] * corr + p * Vs[j][lane + 32 * i];
            mi = mnew;
        }
    }

    float inv = 1.f / li;
    #pragma unroll
    for (int i = 0; i < 4; i++)
        Ob[(size_t)qrow * DIM + lane + 32 * i] = acc[i] * inv;
}

// ---------------------------------------------------------------------------
// Launch
// ---------------------------------------------------------------------------
extern "C" void kernel_launch(void* const* d_in, const int* in_sizes, int n_in,
                              void* d_out, int out_size)
{
    const float* x       = (const float*)d_in[0];
    const float* Wr_in   = (const float*)d_in[2];
    const float* Wr_proc = (const float*)d_in[3];
    const float* Wr_out  = (const float*)d_in[4];
    const float* WrO_in  = (const float*)d_in[5];
    const float* WrO_proc= (const float*)d_in[6];
    const float* WrO_out = (const float*)d_in[7];
    const float* Wq_in   = (const float*)d_in[8];
    const float* vq      = (const float*)d_in[9];
    const float* Wq_out  = (const float*)d_in[10];
    const float* Wk_in   = (const float*)d_in[11];
    const float* vk      = (const float*)d_in[12];
    const float* Wk_out  = (const float*)d_in[13];
    const float* Wv_in   = (const float*)d_in[14];
    const float* vv      = (const float*)d_in[15];
    const float* Wv_out  = (const float*)d_in[16];
    const float* Wo_in   = (const float*)d_in[17];
    const float* vo      = (const float*)d_in[18];
    const float* Wo_out  = (const float*)d_in[19];
    float* out = (float*)d_out;

    float *h, *Q, *Kc, *V, *O, *inw, *outw;
    int* pidx;
    __nv_bfloat16 *whi, *wlo, *xhi, *xlo, *hhi, *hlo;
    cudaGetSymbolAddress((void**)&h,    g_h);
    cudaGetSymbolAddress((void**)&Q,    g_Q);
    cudaGetSymbolAddress((void**)&Kc,   g_Kc);
    cudaGetSymbolAddress((void**)&V,    g_V);
    cudaGetSymbolAddress((void**)&O,    g_O);
    cudaGetSymbolAddress((void**)&inw,  g_inw);
    cudaGetSymbolAddress((void**)&outw, g_outw);
    cudaGetSymbolAddress((void**)&pidx, g_pidx);
    cudaGetSymbolAddress((void**)&whi,  g_whi);
    cudaGetSymbolAddress((void**)&wlo,  g_wlo);
    cudaGetSymbolAddress((void**)&xhi,  g_xhi);
    cudaGetSymbolAddress((void**)&xlo,  g_xlo);
    cudaGetSymbolAddress((void**)&hhi,  g_hhi);
    cudaGetSymbolAddress((void**)&hlo,  g_hlo);

    cudaFuncSetAttribute(circuit_gemm_tc,
                         cudaFuncAttributeMaxDynamicSharedMemorySize,
                         SMEM_GEMM_BYTES);

    dim3 gGemm(DIM / 128, TOK / 128);     // (8, 32)
    dim3 gPrep(DIM / 32, KTOT / 32);      // (32, 256)
    int  gSplit = TOK * DIM / (256 * 4);  // 4096

    auto gemm = [&](const __nv_bfloat16* ah, const __nv_bfloat16* al,
                    const float* W, const float* wg, float* o) {
        prep_w_kernel<<<gPrep, 256>>>(W, whi, wlo);
        circuit_gemm_tc<<<gGemm, 256, SMEM_GEMM_BYTES>>>(ah, al, whi, wlo, wg, o);
    };

    // Router on x + x split
    router_kernel<<<TOK, 128>>>(x, Wr_in, Wr_proc, Wr_out, inw, pidx, outw);
    split_kernel<<<gSplit, 256>>>(x, xhi, xlo);

    // Q circuit
    gemm(xhi, xlo, Wq_in, inw, h);
    householder_kernel<<<TOK, 256>>>(h, vq, pidx, hhi, hlo);
    gemm(hhi, hlo, Wq_out, outw, Q);

    // K circuit
    gemm(xhi, xlo, Wk_in, inw, h);
    householder_kernel<<<TOK, 256>>>(h, vk, pidx, hhi, hlo);
    gemm(hhi, hlo, Wk_out, outw, Kc);

    // V circuit
    gemm(xhi, xlo, Wv_in, inw, h);
    householder_kernel<<<TOK, 256>>>(h, vv, pidx, hhi, hlo);
    gemm(hhi, hlo, Wv_out, outw, V);

    // Attention
    attn_kernel<<<dim3(SEQ / 8, NBATCH * NH), 256>>>(Q, Kc, V, O);

    // Router on O + output circuit (reuse x split buffers)
    router_kernel<<<TOK, 128>>>(O, WrO_in, WrO_proc, WrO_out, inw, pidx, outw);
    split_kernel<<<gSplit, 256>>>(O, xhi, xlo);
    gemm(xhi, xlo, Wo_in, inw, h);
    householder_kernel<<<TOK, 256>>>(h, vo, pidx, hhi, hlo);
    gemm(hhi, hlo, Wo_out, outw, out);

    (void)in_sizes; (void)n_in; (void)out_size;
}

// round 6
// speedup vs baseline: 2.0003x; 1.1481x over previous
#include <cuda_runtime.h>
#include <cuda_bf16.h>
#include <math.h>
#include <stdint.h>

// Problem constants
#define TOK   4096      // B*S
#define DIM   1024      // D == R
#define SEQ   2048
#define NBATCH 2
#define NH    8
#define DHEAD 128
#define NEXP  8
#define NPROC 32
#define TOPK  3
#define KTOT  8192      // NEXP * DIM

// GEMM tiling
#define BK      64
#define NCHUNK  (KTOT / BK)           // 128
#define PAD     72                    // smem row stride in bf16 halves
#define MAT_BYTES   (128 * PAD * 2)   // 18432 per matrix
#define STAGE_BYTES (4 * MAT_BYTES)   // Ahi, Alo, Bhi, Blo
#define NSTAGE  3
#define SMEM_GEMM_BYTES (NSTAGE * STAGE_BYTES)   // 221184

// ---------------------------------------------------------------------------
// Scratch (device globals — no runtime allocation allowed)
// ---------------------------------------------------------------------------
__device__ float g_h  [TOK * DIM];
__device__ float g_Q  [TOK * DIM];
__device__ float g_Kc [TOK * DIM];
__device__ float g_V  [TOK * DIM];
__device__ float g_O  [TOK * DIM];
__device__ float g_inw [TOK * NEXP];
__device__ float g_outw[TOK * NEXP];
__device__ int   g_pidx[TOK * TOPK];
__device__ __nv_bfloat16 g_whi[DIM * KTOT];   // weightT hi [N=1024, K=8192]
__device__ __nv_bfloat16 g_wlo[DIM * KTOT];
__device__ __nv_bfloat16 g_xhi[TOK * DIM];    // activation split (x / O)
__device__ __nv_bfloat16 g_xlo[TOK * DIM];
__device__ __nv_bfloat16 g_hhi[TOK * DIM];    // householder output split
__device__ __nv_bfloat16 g_hlo[TOK * DIM];

// ---------------------------------------------------------------------------
// Portable tensor-core helpers (sm_80+ PTX; no 'a'-suffix features)
// ---------------------------------------------------------------------------
#define LDSM4(r0, r1, r2, r3, addr) \
    asm volatile("ldmatrix.sync.aligned.m8n8.x4.shared.b16 {%0,%1,%2,%3}, [%4];" \
                 : "=r"(r0), "=r"(r1), "=r"(r2), "=r"(r3) : "r"(addr))

__device__ __forceinline__ void mma_bf16(float* c, const uint32_t* a, const uint32_t* b) {
    asm volatile(
        "mma.sync.aligned.m16n8k16.row.col.f32.bf16.bf16.f32 "
        "{%0,%1,%2,%3}, {%4,%5,%6,%7}, {%8,%9}, {%0,%1,%2,%3};"
        : "+f"(c[0]), "+f"(c[1]), "+f"(c[2]), "+f"(c[3])
        : "r"(a[0]), "r"(a[1]), "r"(a[2]), "r"(a[3]), "r"(b[0]), "r"(b[1]));
}

__device__ __forceinline__ void cp16(uint32_t saddr, const void* gaddr) {
    asm volatile("cp.async.cg.shared.global [%0], [%1], 16;" :: "r"(saddr), "l"(gaddr));
}
__device__ __forceinline__ void cp_commit() {
    asm volatile("cp.async.commit_group;" ::: "memory");
}
template <int N>
__device__ __forceinline__ void cp_wait() {
    asm volatile("cp.async.wait_group %0;" :: "n"(N) : "memory");
}

__device__ __forceinline__ void split_bf16(float v, __nv_bfloat16& hi, __nv_bfloat16& lo) {
    hi = __float2bfloat16_rn(v);
    lo = __float2bfloat16_rn(v - __bfloat162float(hi));
}

// ---------------------------------------------------------------------------
// Weight prep: W[KTOT, DIM] fp32 -> transposed bf16 hi/lo [DIM, KTOT]
// ---------------------------------------------------------------------------
__global__ void prep_w_kernel(const float* __restrict__ W,
                              __nv_bfloat16* __restrict__ Whi,
                              __nv_bfloat16* __restrict__ Wlo)
{
    __shared__ float ts[32][33];
    int k0 = blockIdx.y * 32, n0 = blockIdx.x * 32;
    int tx = threadIdx.x & 31, ty = threadIdx.x >> 5;   // 32 x 8
    #pragma unroll
    for (int r = 0; r < 4; r++) {
        int k = ty + r * 8;
        ts[k][tx] = W[(size_t)(k0 + k) * DIM + n0 + tx];
    }
    __syncthreads();
    #pragma unroll
    for (int r = 0; r < 4; r++) {
        int n = ty + r * 8;
        float v = ts[tx][n];                      // W[k0+tx][n0+n]
        __nv_bfloat16 h, l;
        split_bf16(v, h, l);
        size_t o = (size_t)(n0 + n) * KTOT + k0 + tx;
        Whi[o] = h;
        Wlo[o] = l;
    }
}

// ---------------------------------------------------------------------------
// Activation split: fp32 [TOK,DIM] -> bf16 hi/lo
// ---------------------------------------------------------------------------
__global__ void split_kernel(const float* __restrict__ src,
                             __nv_bfloat16* __restrict__ hi,
                             __nv_bfloat16* __restrict__ lo)
{
    int i = (blockIdx.x * 256 + threadIdx.x) * 4;
    float4 v = *(const float4*)(src + i);
    __nv_bfloat16 h[4], l[4];
    split_bf16(v.x, h[0], l[0]);
    split_bf16(v.y, h[1], l[1]);
    split_bf16(v.z, h[2], l[2]);
    split_bf16(v.w, h[3], l[3]);
    *(uint64_t*)(hi + i) = *(uint64_t*)h;
    *(uint64_t*)(lo + i) = *(uint64_t*)l;
}

// ---------------------------------------------------------------------------
// Tensor-core mixture GEMM via mma.sync (split-bf16, 3 passes, fp32 acc).
// 512 threads / 16 warps: 4(M) x 4(N) warp grid, 32x32 warp tile.
// A = unscaled split activation (columns cycle mod 1024); expert scale
// applied in registers at expert-segment boundaries.
// ---------------------------------------------------------------------------
__global__ __launch_bounds__(512)
void circuit_gemm_tc(const __nv_bfloat16* __restrict__ Ahi,  // [TOK, DIM]
                     const __nv_bfloat16* __restrict__ Alo,
                     const __nv_bfloat16* __restrict__ Whi,  // [N, K]
                     const __nv_bfloat16* __restrict__ Wlo,
                     const float* __restrict__ wgt,          // [TOK, NEXP]
                     float* __restrict__ out)                // [TOK, DIM]
{
    extern __shared__ char smem[];
    __shared__ float swgt[128 * NEXP];
    const uint32_t sb = (uint32_t)__cvta_generic_to_shared(smem);
    int tid = threadIdx.x, lane = tid & 31, wid = tid >> 5;
    int bm = blockIdx.y * 128, bn = blockIdx.x * 128;

    // ---- loader role: 4 threads per row, 16-k quarter each ----
    int r  = tid >> 2;                 // 0..127
    int kq = (tid & 3) * 16;           // k quarter
    const __nv_bfloat16* ahip = Ahi + (size_t)(bm + r) * DIM + kq;
    const __nv_bfloat16* alop = Alo + (size_t)(bm + r) * DIM + kq;
    const __nv_bfloat16* bhip = Whi + (size_t)(bn + r) * KTOT + kq;
    const __nv_bfloat16* blop = Wlo + (size_t)(bn + r) * KTOT + kq;
    const uint32_t rowoff = (uint32_t)(r * PAD + kq) * 2;

    auto load_chunk = [&](int c) {
        uint32_t st = sb + (uint32_t)(c % NSTAGE) * STAGE_BYTES;
        int k0 = c * BK;
        int d0 = k0 & (DIM - 1);
        #pragma unroll
        for (int ci = 0; ci < 2; ci++) {
            cp16(st + rowoff + ci * 16,                 ahip + d0 + ci * 8);
            cp16(st + MAT_BYTES + rowoff + ci * 16,     alop + d0 + ci * 8);
            cp16(st + 2 * MAT_BYTES + rowoff + ci * 16, bhip + k0 + ci * 8);
            cp16(st + 3 * MAT_BYTES + rowoff + ci * 16, blop + k0 + ci * 8);
        }
        cp_commit();
    };

    // ---- compute role: 4(M) x 4(N) warp grid, 32x32 warp tile ----
    int wm = (wid >> 2) * 32;
    int wn = (wid & 3) * 32;
    int arow = lane & 15;
    int acol = (lane >> 4) * 8;
    int q    = lane >> 3, rl = lane & 7;
    int brow = wn + ((q >= 2) ? 8 : 0) + rl;
    int bcol = (q & 1) * 8;
    const uint32_t aOff = (uint32_t)((wm + arow) * PAD + acol) * 2;
    const uint32_t bOff = (uint32_t)(2 * MAT_BYTES) + (uint32_t)(brow * PAD + bcol) * 2;
    int g = lane >> 2;

    float acc[2][4][4];
    float seg[2][4][4];
    #pragma unroll
    for (int i = 0; i < 2; i++)
        #pragma unroll
        for (int j = 0; j < 4; j++)
            #pragma unroll
            for (int e = 0; e < 4; e++) acc[i][j][e] = 0.f;

    // ---- prologue ----
    for (int idx = tid; idx < 128 * NEXP; idx += 512)
        swgt[idx] = wgt[(size_t)(bm + (idx >> 3)) * NEXP + (idx & 7)];
    load_chunk(0);
    load_chunk(1);

    int c = 0;
    for (int e = 0; e < NEXP; e++) {
        #pragma unroll
        for (int i = 0; i < 2; i++)
            #pragma unroll
            for (int j = 0; j < 4; j++)
                #pragma unroll
                for (int t = 0; t < 4; t++) seg[i][j][t] = 0.f;

        for (int dc = 0; dc < 16; dc++, c++) {
            if (c + 1 < NCHUNK) cp_wait<1>(); else cp_wait<0>();
            __syncthreads();
            if (c + 2 < NCHUNK) load_chunk(c + 2);

            uint32_t st = sb + (uint32_t)(c % NSTAGE) * STAGE_BYTES;
            uint32_t aHi = st + aOff;
            uint32_t bHi = st + bOff;

            #pragma unroll
            for (int ks = 0; ks < 4; ks++) {
                uint32_t kb = (uint32_t)(ks * 16) * 2;
                uint32_t bh[4][2], bl[4][2];
                #pragma unroll
                for (int p = 0; p < 2; p++) {
                    uint32_t ba = bHi + (uint32_t)(p * 16 * PAD) * 2 + kb;
                    LDSM4(bh[2*p][0], bh[2*p][1], bh[2*p+1][0], bh[2*p+1][1], ba);
                    LDSM4(bl[2*p][0], bl[2*p][1], bl[2*p+1][0], bl[2*p+1][1], ba + MAT_BYTES);
                }
                #pragma unroll
                for (int mt = 0; mt < 2; mt++) {
                    uint32_t aa = aHi + (uint32_t)(mt * 16 * PAD) * 2 + kb;
                    uint32_t ah[4], al[4];
                    LDSM4(ah[0], ah[1], ah[2], ah[3], aa);
                    LDSM4(al[0], al[1], al[2], al[3], aa + MAT_BYTES);
                    #pragma unroll
                    for (int nt = 0; nt < 4; nt++) {
                        mma_bf16(seg[mt][nt], ah, bh[nt]);
                        mma_bf16(seg[mt][nt], ah, bl[nt]);
                        mma_bf16(seg[mt][nt], al, bh[nt]);
                    }
                }
            }
        }

        // ---- expert boundary: acc += w(row, e) * seg ----
        #pragma unroll
        for (int mt = 0; mt < 2; mt++) {
            float w0 = swgt[(wm + mt * 16 + g) * NEXP + e];
            float w1 = swgt[(wm + mt * 16 + 8 + g) * NEXP + e];
            #pragma unroll
            for (int nt = 0; nt < 4; nt++) {
                acc[mt][nt][0] += w0 * seg[mt][nt][0];
                acc[mt][nt][1] += w0 * seg[mt][nt][1];
                acc[mt][nt][2] += w1 * seg[mt][nt][2];
                acc[mt][nt][3] += w1 * seg[mt][nt][3];
            }
        }
    }

    // ---- epilogue ----
    int tig = lane & 3;
    #pragma unroll
    for (int mt = 0; mt < 2; mt++) {
        #pragma unroll
        for (int nt = 0; nt < 4; nt++) {
            int row = bm + wm + mt * 16 + g;
            int col = bn + wn + nt * 8 + tig * 2;
            *(float2*)(out + (size_t)row * DIM + col) =
                make_float2(acc[mt][nt][0], acc[mt][nt][1]);
            *(float2*)(out + (size_t)(row + 8) * DIM + col) =
                make_float2(acc[mt][nt][2], acc[mt][nt][3]);
        }
    }
}

// ---------------------------------------------------------------------------
// Router: 48 logits per token (8 in / 32 proc / 8 out), softmax8 x2 + top-3
// ---------------------------------------------------------------------------
__global__ void router_kernel(const float* __restrict__ act,
                              const float* __restrict__ Wi,
                              const float* __restrict__ Wp,
                              const float* __restrict__ Wo,
                              float* __restrict__ inw,
                              int*   __restrict__ pidx,
                              float* __restrict__ outw)
{
    int t    = blockIdx.x;
    int tid  = threadIdx.x;
    int lane = tid & 31, warp = tid >> 5;
    __shared__ float xs[DIM];
    __shared__ float lg[48];

    const float* xr = act + (size_t)t * DIM;
    for (int i = tid; i < DIM; i += 128) xs[i] = xr[i];
    __syncthreads();

    for (int l = warp; l < 48; l += 4) {
        const float* wr = (l < 8) ? (Wi + (size_t)l * DIM)
                        : (l < 40) ? (Wp + (size_t)(l - 8) * DIM)
                                   : (Wo + (size_t)(l - 40) * DIM);
        float s = 0.f;
        for (int d = lane; d < DIM; d += 32) s += xs[d] * wr[d];
        #pragma unroll
        for (int off = 16; off > 0; off >>= 1)
            s += __shfl_xor_sync(0xffffffffu, s, off);
        if (lane == 0) lg[l] = s;
    }
    __syncthreads();

    if (tid == 0) {
        float m = lg[0];
        for (int i = 1; i < 8; i++) m = fmaxf(m, lg[i]);
        float e[8], sum = 0.f;
        for (int i = 0; i < 8; i++) { e[i] = expf(lg[i] - m); sum += e[i]; }
        for (int i = 0; i < 8; i++) inw[t * 8 + i] = e[i] / sum;

        bool used[NPROC];
        for (int n = 0; n < NPROC; n++) used[n] = false;
        for (int r = 0; r < TOPK; r++) {
            float best = -INFINITY; int bi = 0;
            for (int n = 0; n < NPROC; n++)
                if (!used[n] && lg[8 + n] > best) { best = lg[8 + n]; bi = n; }
            used[bi] = true;
            pidx[t * TOPK + r] = bi;
        }

        m = lg[40];
        for (int i = 1; i < 8; i++) m = fmaxf(m, lg[40 + i]);
        sum = 0.f;
        for (int i = 0; i < 8; i++) { e[i] = expf(lg[40 + i] - m); sum += e[i]; }
        for (int i = 0; i < 8; i++) outw[t * 8 + i] = e[i] / sum;
    }
}

// ---------------------------------------------------------------------------
// Householder reflections: h -= 2 (h.v)/(v.v + 1e-8) v, 3x per token;
// writes split bf16 hi/lo output.
// ---------------------------------------------------------------------------
__global__ void householder_kernel(const float* __restrict__ hbuf,
                                   const float* __restrict__ vproc,
                                   const int* __restrict__ pidx,
                                   __nv_bfloat16* __restrict__ ohi,
                                   __nv_bfloat16* __restrict__ olo)
{
    int t = blockIdx.x, tid = threadIdx.x;
    int lane = tid & 31, warp = tid >> 5;
    const float* hr = hbuf + (size_t)t * DIM;

    float hv[4];
    #pragma unroll
    for (int i = 0; i < 4; i++) hv[i] = hr[tid + 256 * i];

    __shared__ float sred[16];

    for (int rfl = 0; rfl < TOPK; rfl++) {
        int idx = pidx[t * TOPK + rfl];
        const float* v = vproc + (size_t)idx * DIM;
        float vr[4];
        float d1 = 0.f, d2 = 0.f;
        #pragma unroll
        for (int i = 0; i < 4; i++) {
            vr[i] = v[tid + 256 * i];
            d1 += hv[i] * vr[i];
            d2 += vr[i] * vr[i];
        }
        #pragma unroll
        for (int off = 16; off > 0; off >>= 1) {
            d1 += __shfl_xor_sync(0xffffffffu, d1, off);
            d2 += __shfl_xor_sync(0xffffffffu, d2, off);
        }
        if (lane == 0) { sred[warp] = d1; sred[8 + warp] = d2; }
        __syncthreads();
        float t1 = 0.f, t2 = 0.f;
        #pragma unroll
        for (int w = 0; w < 8; w++) { t1 += sred[w]; t2 += sred[8 + w]; }
        float f = 2.f * t1 / (t2 + 1e-8f);
        #pragma unroll
        for (int i = 0; i < 4; i++) hv[i] -= f * vr[i];
        __syncthreads();
    }

    #pragma unroll
    for (int i = 0; i < 4; i++) {
        __nv_bfloat16 h, l;
        split_bf16(hv[i], h, l);
        ohi[(size_t)t * DIM + tid + 256 * i] = h;
        olo[(size_t)t * DIM + tid + 256 * i] = l;
    }
}

// ---------------------------------------------------------------------------
// Causal attention, online softmax (fp32), warp-per-query-row
// ---------------------------------------------------------------------------
__global__ void attn_kernel(const float* __restrict__ Q,
                            const float* __restrict__ K,
                            const float* __restrict__ V,
                            float* __restrict__ O)
{
    const float scale = 0.08838834764831845f;  // 1/sqrt(128)
    int bh = blockIdx.y;
    int b = bh >> 3, hh = bh & 7;
    int q0 = blockIdx.x * 8;
    int tid = threadIdx.x, lane = tid & 31, warp = tid >> 5;

    const float* Qb = Q + (size_t)b * SEQ * DIM + hh * DHEAD;
    const float* Kb = K + (size_t)b * SEQ * DIM + hh * DHEAD;
    const float* Vb = V + (size_t)b * SEQ * DIM + hh * DHEAD;
    float*       Ob = O + (size_t)b * SEQ * DIM + hh * DHEAD;

    int qrow = q0 + warp;
    float q[4], acc[4] = {0.f, 0.f, 0.f, 0.f};
    #pragma unroll
    for (int i = 0; i < 4; i++) q[i] = Qb[(size_t)qrow * DIM + lane + 32 * i];

    float mi = -1e30f, li = 0.f;

    __shared__ float Ks[32][DHEAD];
    __shared__ float Vs[32][DHEAD];

    int kend = q0 + 8;
    for (int c0 = 0; c0 < kend; c0 += 32) {
        __syncthreads();
        for (int idx = tid; idx < 32 * DHEAD; idx += 256) {
            int j = idx >> 7, d = idx & 127;
            Ks[j][d] = Kb[(size_t)(c0 + j) * DIM + d];
            Vs[j][d] = Vb[(size_t)(c0 + j) * DIM + d];
        }
        __syncthreads();

        int jend = min(32, kend - c0);
        for (int j = 0; j < jend; j++) {
            int kg = c0 + j;
            if (kg > qrow) break;
            float s = q[0] * Ks[j][lane]      + q[1] * Ks[j][lane + 32]
                    + q[2] * Ks[j][lane + 64] + q[3] * Ks[j][lane + 96];
            #pragma unroll
            for (int off = 16; off > 0; off >>= 1)
                s += __shfl_xor_sync(0xffffffffu, s, off);
            s *= scale;
            float mnew = fmaxf(mi, s);
            float corr = expf(mi - mnew);
            float p    = expf(s - mnew);
            li = li * corr + p;
            #pragma unroll
            for (int i = 0; i < 4; i++)
                acc[i] = acc[i] * corr + p * Vs[j][lane + 32 * i];
            mi = mnew;
        }
    }

    float inv = 1.f / li;
    #pragma unroll
    for (int i = 0; i < 4; i++)
        Ob[(size_t)qrow * DIM + lane + 32 * i] = acc[i] * inv;
}

// ---------------------------------------------------------------------------
// Launch
// ---------------------------------------------------------------------------
extern "C" void kernel_launch(void* const* d_in, const int* in_sizes, int n_in,
                              void* d_out, int out_size)
{
    const float* x       = (const float*)d_in[0];
    const float* Wr_in   = (const float*)d_in[2];
    const float* Wr_proc = (const float*)d_in[3];
    const float* Wr_out  = (const float*)d_in[4];
    const float* WrO_in  = (const float*)d_in[5];
    const float* WrO_proc= (const float*)d_in[6];
    const float* WrO_out = (const float*)d_in[7];
    const float* Wq_in   = (const float*)d_in[8];
    const float* vq      = (const float*)d_in[9];
    const float* Wq_out  = (const float*)d_in[10];
    const float* Wk_in   = (const float*)d_in[11];
    const float* vk      = (const float*)d_in[12];
    const float* Wk_out  = (const float*)d_in[13];
    const float* Wv_in   = (const float*)d_in[14];
    const float* vv      = (const float*)d_in[15];
    const float* Wv_out  = (const float*)d_in[16];
    const float* Wo_in   = (const float*)d_in[17];
    const float* vo      = (const float*)d_in[18];
    const float* Wo_out  = (const float*)d_in[19];
    float* out = (float*)d_out;

    float *h, *Q, *Kc, *V, *O, *inw, *outw;
    int* pidx;
    __nv_bfloat16 *whi, *wlo, *xhi, *xlo, *hhi, *hlo;
    cudaGetSymbolAddress((void**)&h,    g_h);
    cudaGetSymbolAddress((void**)&Q,    g_Q);
    cudaGetSymbolAddress((void**)&Kc,   g_Kc);
    cudaGetSymbolAddress((void**)&V,    g_V);
    cudaGetSymbolAddress((void**)&O,    g_O);
    cudaGetSymbolAddress((void**)&inw,  g_inw);
    cudaGetSymbolAddress((void**)&outw, g_outw);
    cudaGetSymbolAddress((void**)&pidx, g_pidx);
    cudaGetSymbolAddress((void**)&whi,  g_whi);
    cudaGetSymbolAddress((void**)&wlo,  g_wlo);
    cudaGetSymbolAddress((void**)&xhi,  g_xhi);
    cudaGetSymbolAddress((void**)&xlo,  g_xlo);
    cudaGetSymbolAddress((void**)&hhi,  g_hhi);
    cudaGetSymbolAddress((void**)&hlo,  g_hlo);

    cudaFuncSetAttribute(circuit_gemm_tc,
                         cudaFuncAttributeMaxDynamicSharedMemorySize,
                         SMEM_GEMM_BYTES);

    dim3 gGemm(DIM / 128, TOK / 128);     // (8, 32)
    dim3 gPrep(DIM / 32, KTOT / 32);      // (32, 256)
    int  gSplit = TOK * DIM / (256 * 4);  // 4096

    auto gemm = [&](const __nv_bfloat16* ah, const __nv_bfloat16* al,
                    const float* W, const float* wg, float* o) {
        prep_w_kernel<<<gPrep, 256>>>(W, whi, wlo);
        circuit_gemm_tc<<<gGemm, 512, SMEM_GEMM_BYTES>>>(ah, al, whi, wlo, wg, o);
    };

    // Router on x + x split
    router_kernel<<<TOK, 128>>>(x, Wr_in, Wr_proc, Wr_out, inw, pidx, outw);
    split_kernel<<<gSplit, 256>>>(x, xhi, xlo);

    // Q circuit
    gemm(xhi, xlo, Wq_in, inw, h);
    householder_kernel<<<TOK, 256>>>(h, vq, pidx, hhi, hlo);
    gemm(hhi, hlo, Wq_out, outw, Q);

    // K circuit
    gemm(xhi, xlo, Wk_in, inw, h);
    householder_kernel<<<TOK, 256>>>(h, vk, pidx, hhi, hlo);
    gemm(hhi, hlo, Wk_out, outw, Kc);

    // V circuit
    gemm(xhi, xlo, Wv_in, inw, h);
    householder_kernel<<<TOK, 256>>>(h, vv, pidx, hhi, hlo);
    gemm(hhi, hlo, Wv_out, outw, V);

    // Attention
    attn_kernel<<<dim3(SEQ / 8, NBATCH * NH), 256>>>(Q, Kc, V, O);

    // Router on O + output circuit (reuse x split buffers)
    router_kernel<<<TOK, 128>>>(O, WrO_in, WrO_proc, WrO_out, inw, pidx, outw);
    split_kernel<<<gSplit, 256>>>(O, xhi, xlo);
    gemm(xhi, xlo, Wo_in, inw, h);
    householder_kernel<<<TOK, 256>>>(h, vo, pidx, hhi, hlo);
    gemm(hhi, hlo, Wo_out, outw, out);

    (void)in_sizes; (void)n_in; (void)out_size;
}

// round 7
// speedup vs baseline: 2.2961x; 1.1479x over previous
#include <cuda_runtime.h>
#include <cuda_bf16.h>
#include <math.h>
#include <stdint.h>

// Problem constants
#define TOK   4096      // B*S
#define DIM   1024      // D == R
#define SEQ   2048
#define NBATCH 2
#define NH    8
#define DHEAD 128
#define NEXP  8
#define NPROC 32
#define TOPK  3
#define KTOT  8192      // NEXP * DIM

// GEMM tiling
#define BK      64
#define NCHUNK  (KTOT / BK)           // 128
#define PAD     72                    // smem row stride in bf16 halves
#define MAT_BYTES   (128 * PAD * 2)   // 18432 per matrix
#define STAGE_BYTES (4 * MAT_BYTES)   // Ahi, Alo, Bhi, Blo
#define NSTAGE  3
#define SMEM_GEMM_BYTES (NSTAGE * STAGE_BYTES)   // 221184

// ---------------------------------------------------------------------------
// Scratch (device globals — no runtime allocation allowed)
// ---------------------------------------------------------------------------
__device__ float g_h  [TOK * DIM];
__device__ float g_Q  [TOK * DIM];
__device__ float g_Kc [TOK * DIM];
__device__ float g_V  [TOK * DIM];
__device__ float g_O  [TOK * DIM];
__device__ float g_inw [TOK * NEXP];
__device__ float g_outw[TOK * NEXP];
__device__ int   g_pidx[TOK * TOPK];
__device__ __nv_bfloat16 g_whi[DIM * KTOT];   // weightT hi [N=1024, K=8192]
__device__ __nv_bfloat16 g_wlo[DIM * KTOT];
__device__ __nv_bfloat16 g_xhi[TOK * DIM];    // activation split (x / O)
__device__ __nv_bfloat16 g_xlo[TOK * DIM];
__device__ __nv_bfloat16 g_hhi[TOK * DIM];    // householder output split
__device__ __nv_bfloat16 g_hlo[TOK * DIM];

// ---------------------------------------------------------------------------
// Portable tensor-core helpers (sm_80+ PTX; no 'a'-suffix features)
// ---------------------------------------------------------------------------
#define LDSM4(r0, r1, r2, r3, addr) \
    asm volatile("ldmatrix.sync.aligned.m8n8.x4.shared.b16 {%0,%1,%2,%3}, [%4];" \
                 : "=r"(r0), "=r"(r1), "=r"(r2), "=r"(r3) : "r"(addr))

__device__ __forceinline__ void mma_bf16(float* c, const uint32_t* a, const uint32_t* b) {
    asm volatile(
        "mma.sync.aligned.m16n8k16.row.col.f32.bf16.bf16.f32 "
        "{%0,%1,%2,%3}, {%4,%5,%6,%7}, {%8,%9}, {%0,%1,%2,%3};"
        : "+f"(c[0]), "+f"(c[1]), "+f"(c[2]), "+f"(c[3])
        : "r"(a[0]), "r"(a[1]), "r"(a[2]), "r"(a[3]), "r"(b[0]), "r"(b[1]));
}

__device__ __forceinline__ void cp16(uint32_t saddr, const void* gaddr) {
    asm volatile("cp.async.cg.shared.global [%0], [%1], 16;" :: "r"(saddr), "l"(gaddr));
}
__device__ __forceinline__ void cp_commit() {
    asm volatile("cp.async.commit_group;" ::: "memory");
}
template <int N>
__device__ __forceinline__ void cp_wait() {
    asm volatile("cp.async.wait_group %0;" :: "n"(N) : "memory");
}

__device__ __forceinline__ void split_bf16(float v, __nv_bfloat16& hi, __nv_bfloat16& lo) {
    hi = __float2bfloat16_rn(v);
    lo = __float2bfloat16_rn(v - __bfloat162float(hi));
}

// ---------------------------------------------------------------------------
// Weight prep: W[KTOT, DIM] fp32 -> transposed bf16 hi/lo [DIM, KTOT]
// ---------------------------------------------------------------------------
__global__ void prep_w_kernel(const float* __restrict__ W,
                              __nv_bfloat16* __restrict__ Whi,
                              __nv_bfloat16* __restrict__ Wlo)
{
    __shared__ float ts[32][33];
    int k0 = blockIdx.y * 32, n0 = blockIdx.x * 32;
    int tx = threadIdx.x & 31, ty = threadIdx.x >> 5;   // 32 x 8
    #pragma unroll
    for (int r = 0; r < 4; r++) {
        int k = ty + r * 8;
        ts[k][tx] = W[(size_t)(k0 + k) * DIM + n0 + tx];
    }
    __syncthreads();
    #pragma unroll
    for (int r = 0; r < 4; r++) {
        int n = ty + r * 8;
        float v = ts[tx][n];                      // W[k0+tx][n0+n]
        __nv_bfloat16 h, l;
        split_bf16(v, h, l);
        size_t o = (size_t)(n0 + n) * KTOT + k0 + tx;
        Whi[o] = h;
        Wlo[o] = l;
    }
}

// ---------------------------------------------------------------------------
// Activation split: fp32 [TOK,DIM] -> bf16 hi/lo
// ---------------------------------------------------------------------------
__global__ void split_kernel(const float* __restrict__ src,
                             __nv_bfloat16* __restrict__ hi,
                             __nv_bfloat16* __restrict__ lo)
{
    int i = (blockIdx.x * 256 + threadIdx.x) * 4;
    float4 v = *(const float4*)(src + i);
    __nv_bfloat16 h[4], l[4];
    split_bf16(v.x, h[0], l[0]);
    split_bf16(v.y, h[1], l[1]);
    split_bf16(v.z, h[2], l[2]);
    split_bf16(v.w, h[3], l[3]);
    *(uint64_t*)(hi + i) = *(uint64_t*)h;
    *(uint64_t*)(lo + i) = *(uint64_t*)l;
}

// ---------------------------------------------------------------------------
// Tensor-core mixture GEMM via mma.sync (split-bf16, 3 passes, fp32 acc).
// 512 threads / 16 warps: 4(M) x 4(N) warp grid, 32x32 warp tile.
// Pass-major MMA issue order: 8 independent accumulators between reuses.
// ---------------------------------------------------------------------------
__global__ __launch_bounds__(512)
void circuit_gemm_tc(const __nv_bfloat16* __restrict__ Ahi,  // [TOK, DIM]
                     const __nv_bfloat16* __restrict__ Alo,
                     const __nv_bfloat16* __restrict__ Whi,  // [N, K]
                     const __nv_bfloat16* __restrict__ Wlo,
                     const float* __restrict__ wgt,          // [TOK, NEXP]
                     float* __restrict__ out)                // [TOK, DIM]
{
    extern __shared__ char smem[];
    __shared__ float swgt[128 * NEXP];
    const uint32_t sb = (uint32_t)__cvta_generic_to_shared(smem);
    int tid = threadIdx.x, lane = tid & 31, wid = tid >> 5;
    int bm = blockIdx.y * 128, bn = blockIdx.x * 128;

    // ---- loader role: 4 threads per row, 16-k quarter each ----
    int r  = tid >> 2;                 // 0..127
    int kq = (tid & 3) * 16;           // k quarter
    const __nv_bfloat16* ahip = Ahi + (size_t)(bm + r) * DIM + kq;
    const __nv_bfloat16* alop = Alo + (size_t)(bm + r) * DIM + kq;
    const __nv_bfloat16* bhip = Whi + (size_t)(bn + r) * KTOT + kq;
    const __nv_bfloat16* blop = Wlo + (size_t)(bn + r) * KTOT + kq;
    const uint32_t rowoff = (uint32_t)(r * PAD + kq) * 2;

    auto load_chunk = [&](int c) {
        uint32_t st = sb + (uint32_t)(c % NSTAGE) * STAGE_BYTES;
        int k0 = c * BK;
        int d0 = k0 & (DIM - 1);
        #pragma unroll
        for (int ci = 0; ci < 2; ci++) {
            cp16(st + rowoff + ci * 16,                 ahip + d0 + ci * 8);
            cp16(st + MAT_BYTES + rowoff + ci * 16,     alop + d0 + ci * 8);
            cp16(st + 2 * MAT_BYTES + rowoff + ci * 16, bhip + k0 + ci * 8);
            cp16(st + 3 * MAT_BYTES + rowoff + ci * 16, blop + k0 + ci * 8);
        }
        cp_commit();
    };

    // ---- compute role: 4(M) x 4(N) warp grid, 32x32 warp tile ----
    int wm = (wid >> 2) * 32;
    int wn = (wid & 3) * 32;
    int arow = lane & 15;
    int acol = (lane >> 4) * 8;
    int q    = lane >> 3, rl = lane & 7;
    int brow = wn + ((q >= 2) ? 8 : 0) + rl;
    int bcol = (q & 1) * 8;
    const uint32_t aOff = (uint32_t)((wm + arow) * PAD + acol) * 2;
    const uint32_t bOff = (uint32_t)(2 * MAT_BYTES) + (uint32_t)(brow * PAD + bcol) * 2;
    int g = lane >> 2;

    float acc[2][4][4];
    float seg[2][4][4];
    #pragma unroll
    for (int i = 0; i < 2; i++)
        #pragma unroll
        for (int j = 0; j < 4; j++)
            #pragma unroll
            for (int e = 0; e < 4; e++) acc[i][j][e] = 0.f;

    // ---- prologue ----
    for (int idx = tid; idx < 128 * NEXP; idx += 512)
        swgt[idx] = wgt[(size_t)(bm + (idx >> 3)) * NEXP + (idx & 7)];
    load_chunk(0);
    load_chunk(1);

    int c = 0;
    for (int e = 0; e < NEXP; e++) {
        #pragma unroll
        for (int i = 0; i < 2; i++)
            #pragma unroll
            for (int j = 0; j < 4; j++)
                #pragma unroll
                for (int t = 0; t < 4; t++) seg[i][j][t] = 0.f;

        for (int dc = 0; dc < 16; dc++, c++) {
            if (c + 1 < NCHUNK) cp_wait<1>(); else cp_wait<0>();
            __syncthreads();
            if (c + 2 < NCHUNK) load_chunk(c + 2);

            uint32_t st = sb + (uint32_t)(c % NSTAGE) * STAGE_BYTES;
            uint32_t aHi = st + aOff;
            uint32_t bHi = st + bOff;

            #pragma unroll
            for (int ks = 0; ks < 4; ks++) {
                uint32_t kb = (uint32_t)(ks * 16) * 2;
                uint32_t bh[4][2], bl[4][2];
                #pragma unroll
                for (int p = 0; p < 2; p++) {
                    uint32_t ba = bHi + (uint32_t)(p * 16 * PAD) * 2 + kb;
                    LDSM4(bh[2*p][0], bh[2*p][1], bh[2*p+1][0], bh[2*p+1][1], ba);
                    LDSM4(bl[2*p][0], bl[2*p][1], bl[2*p+1][0], bl[2*p+1][1], ba + MAT_BYTES);
                }
                uint32_t ah[2][4], al[2][4];
                #pragma unroll
                for (int mt = 0; mt < 2; mt++) {
                    uint32_t aa = aHi + (uint32_t)(mt * 16 * PAD) * 2 + kb;
                    LDSM4(ah[mt][0], ah[mt][1], ah[mt][2], ah[mt][3], aa);
                    LDSM4(al[mt][0], al[mt][1], al[mt][2], al[mt][3], aa + MAT_BYTES);
                }
                // pass-major: 8 independent accumulators between same-acc reuse
                #pragma unroll
                for (int mt = 0; mt < 2; mt++)
                    #pragma unroll
                    for (int nt = 0; nt < 4; nt++)
                        mma_bf16(seg[mt][nt], ah[mt], bh[nt]);
                #pragma unroll
                for (int mt = 0; mt < 2; mt++)
                    #pragma unroll
                    for (int nt = 0; nt < 4; nt++)
                        mma_bf16(seg[mt][nt], ah[mt], bl[nt]);
                #pragma unroll
                for (int mt = 0; mt < 2; mt++)
                    #pragma unroll
                    for (int nt = 0; nt < 4; nt++)
                        mma_bf16(seg[mt][nt], al[mt], bh[nt]);
            }
        }

        // ---- expert boundary: acc += w(row, e) * seg ----
        #pragma unroll
        for (int mt = 0; mt < 2; mt++) {
            float w0 = swgt[(wm + mt * 16 + g) * NEXP + e];
            float w1 = swgt[(wm + mt * 16 + 8 + g) * NEXP + e];
            #pragma unroll
            for (int nt = 0; nt < 4; nt++) {
                acc[mt][nt][0] += w0 * seg[mt][nt][0];
                acc[mt][nt][1] += w0 * seg[mt][nt][1];
                acc[mt][nt][2] += w1 * seg[mt][nt][2];
                acc[mt][nt][3] += w1 * seg[mt][nt][3];
            }
        }
    }

    // ---- epilogue ----
    int tig = lane & 3;
    #pragma unroll
    for (int mt = 0; mt < 2; mt++) {
        #pragma unroll
        for (int nt = 0; nt < 4; nt++) {
            int row = bm + wm + mt * 16 + g;
            int col = bn + wn + nt * 8 + tig * 2;
            *(float2*)(out + (size_t)row * DIM + col) =
                make_float2(acc[mt][nt][0], acc[mt][nt][1]);
            *(float2*)(out + (size_t)(row + 8) * DIM + col) =
                make_float2(acc[mt][nt][2], acc[mt][nt][3]);
        }
    }
}

// ---------------------------------------------------------------------------
// Router: 48 logits per token (8 in / 32 proc / 8 out), softmax8 x2 + top-3
// ---------------------------------------------------------------------------
__global__ void router_kernel(const float* __restrict__ act,
                              const float* __restrict__ Wi,
                              const float* __restrict__ Wp,
                              const float* __restrict__ Wo,
                              float* __restrict__ inw,
                              int*   __restrict__ pidx,
                              float* __restrict__ outw)
{
    int t    = blockIdx.x;
    int tid  = threadIdx.x;
    int lane = tid & 31, warp = tid >> 5;
    __shared__ float xs[DIM];
    __shared__ float lg[48];

    const float* xr = act + (size_t)t * DIM;
    for (int i = tid; i < DIM; i += 128) xs[i] = xr[i];
    __syncthreads();

    for (int l = warp; l < 48; l += 4) {
        const float* wr = (l < 8) ? (Wi + (size_t)l * DIM)
                        : (l < 40) ? (Wp + (size_t)(l - 8) * DIM)
                                   : (Wo + (size_t)(l - 40) * DIM);
        float s = 0.f;
        for (int d = lane; d < DIM; d += 32) s += xs[d] * wr[d];
        #pragma unroll
        for (int off = 16; off > 0; off >>= 1)
            s += __shfl_xor_sync(0xffffffffu, s, off);
        if (lane == 0) lg[l] = s;
    }
    __syncthreads();

    if (tid == 0) {
        float m = lg[0];
        for (int i = 1; i < 8; i++) m = fmaxf(m, lg[i]);
        float e[8], sum = 0.f;
        for (int i = 0; i < 8; i++) { e[i] = expf(lg[i] - m); sum += e[i]; }
        for (int i = 0; i < 8; i++) inw[t * 8 + i] = e[i] / sum;

        bool used[NPROC];
        for (int n = 0; n < NPROC; n++) used[n] = false;
        for (int r = 0; r < TOPK; r++) {
            float best = -INFINITY; int bi = 0;
            for (int n = 0; n < NPROC; n++)
                if (!used[n] && lg[8 + n] > best) { best = lg[8 + n]; bi = n; }
            used[bi] = true;
            pidx[t * TOPK + r] = bi;
        }

        m = lg[40];
        for (int i = 1; i < 8; i++) m = fmaxf(m, lg[40 + i]);
        sum = 0.f;
        for (int i = 0; i < 8; i++) { e[i] = expf(lg[40 + i] - m); sum += e[i]; }
        for (int i = 0; i < 8; i++) outw[t * 8 + i] = e[i] / sum;
    }
}

// ---------------------------------------------------------------------------
// Householder reflections: h -= 2 (h.v)/(v.v + 1e-8) v, 3x per token;
// writes split bf16 hi/lo output.
// ---------------------------------------------------------------------------
__global__ void householder_kernel(const float* __restrict__ hbuf,
                                   const float* __restrict__ vproc,
                                   const int* __restrict__ pidx,
                                   __nv_bfloat16* __restrict__ ohi,
                                   __nv_bfloat16* __restrict__ olo)
{
    int t = blockIdx.x, tid = threadIdx.x;
    int lane = tid & 31, warp = tid >> 5;
    const float* hr = hbuf + (size_t)t * DIM;

    float hv[4];
    #pragma unroll
    for (int i = 0; i < 4; i++) hv[i] = hr[tid + 256 * i];

    __shared__ float sred[16];

    for (int rfl = 0; rfl < TOPK; rfl++) {
        int idx = pidx[t * TOPK + rfl];
        const float* v = vproc + (size_t)idx * DIM;
        float vr[4];
        float d1 = 0.f, d2 = 0.f;
        #pragma unroll
        for (int i = 0; i < 4; i++) {
            vr[i] = v[tid + 256 * i];
            d1 += hv[i] * vr[i];
            d2 += vr[i] * vr[i];
        }
        #pragma unroll
        for (int off = 16; off > 0; off >>= 1) {
            d1 += __shfl_xor_sync(0xffffffffu, d1, off);
            d2 += __shfl_xor_sync(0xffffffffu, d2, off);
        }
        if (lane == 0) { sred[warp] = d1; sred[8 + warp] = d2; }
        __syncthreads();
        float t1 = 0.f, t2 = 0.f;
        #pragma unroll
        for (int w = 0; w < 8; w++) { t1 += sred[w]; t2 += sred[8 + w]; }
        float f = 2.f * t1 / (t2 + 1e-8f);
        #pragma unroll
        for (int i = 0; i < 4; i++) hv[i] -= f * vr[i];
        __syncthreads();
    }

    #pragma unroll
    for (int i = 0; i < 4; i++) {
        __nv_bfloat16 h, l;
        split_bf16(hv[i], h, l);
        ohi[(size_t)t * DIM + tid + 256 * i] = h;
        olo[(size_t)t * DIM + tid + 256 * i] = l;
    }
}

// ---------------------------------------------------------------------------
// Causal attention, online softmax (fp32). Lane-per-key within 32-key
// batches: one exp per lane per batch, one shfl broadcast per key for P.V.
// ---------------------------------------------------------------------------
__global__ void attn_kernel(const float* __restrict__ Q,
                            const float* __restrict__ K,
                            const float* __restrict__ V,
                            float* __restrict__ O)
{
    const float scale = 0.08838834764831845f;  // 1/sqrt(128)
    int bh = blockIdx.y;
    int b = bh >> 3, hh = bh & 7;
    int q0 = blockIdx.x * 8;
    int tid = threadIdx.x, lane = tid & 31, warp = tid >> 5;

    const float* Qb = Q + (size_t)b * SEQ * DIM + hh * DHEAD;
    const float* Kb = K + (size_t)b * SEQ * DIM + hh * DHEAD;
    const float* Vb = V + (size_t)b * SEQ * DIM + hh * DHEAD;
    float*       Ob = O + (size_t)b * SEQ * DIM + hh * DHEAD;

    __shared__ float Ks[32][132];   // pad 132: conflict-free per-row float4
    __shared__ float Vs[32][132];
    __shared__ float qs[8][128];

    int qrow = q0 + warp;
    // stage own q row (read back only by this warp)
    #pragma unroll
    for (int i = 0; i < 4; i++)
        qs[warp][lane + 32 * i] = Qb[(size_t)qrow * DIM + lane + 32 * i];

    float acc[4] = {0.f, 0.f, 0.f, 0.f};   // dims lane*4 .. lane*4+3
    float mi = -1e30f, li = 0.f;

    int kend = q0 + 8;   // need keys [0, kend)
    for (int c0 = 0; c0 < kend; c0 += 32) {
        __syncthreads();
        for (int idx = tid; idx < 32 * DHEAD; idx += 256) {
            int j = idx >> 7, d = idx & 127;
            Ks[j][d] = Kb[(size_t)(c0 + j) * DIM + d];
            Vs[j][d] = Vb[(size_t)(c0 + j) * DIM + d];
        }
        __syncthreads();

        // lane handles key c0+lane: full 128-dim dot via float4 smem reads
        int kg = c0 + lane;
        const float4* kr = (const float4*)&Ks[lane][0];
        const float4* qr = (const float4*)&qs[warp][0];
        float s = 0.f;
        #pragma unroll
        for (int w = 0; w < 32; w++) {
            float4 kk = kr[w];
            float4 qq = qr[w];
            s += qq.x * kk.x + qq.y * kk.y + qq.z * kk.z + qq.w * kk.w;
        }
        s *= scale;
        if (kg > qrow) s = -1e30f;   // causal mask (exp -> exact 0)

        // batch max + single exp per lane
        float mb = s;
        #pragma unroll
        for (int off = 16; off > 0; off >>= 1)
            mb = fmaxf(mb, __shfl_xor_sync(0xffffffffu, mb, off));
        float mnew = fmaxf(mi, mb);
        float corr = expf(mi - mnew);
        float p = expf(s - mnew);
        float psum = p;
        #pragma unroll
        for (int off = 16; off > 0; off >>= 1)
            psum += __shfl_xor_sync(0xffffffffu, psum, off);
        li = li * corr + psum;

        #pragma unroll
        for (int i = 0; i < 4; i++) acc[i] *= corr;
        #pragma unroll
        for (int j = 0; j < 32; j++) {
            float pj = __shfl_sync(0xffffffffu, p, j);
            float4 vv = *(const float4*)&Vs[j][lane * 4];
            acc[0] += pj * vv.x;
            acc[1] += pj * vv.y;
            acc[2] += pj * vv.z;
            acc[3] += pj * vv.w;
        }
        mi = mnew;
    }

    float inv = 1.f / li;
    float4 o4 = make_float4(acc[0] * inv, acc[1] * inv, acc[2] * inv, acc[3] * inv);
    *(float4*)(Ob + (size_t)qrow * DIM + lane * 4) = o4;
}

// ---------------------------------------------------------------------------
// Launch
// ---------------------------------------------------------------------------
extern "C" void kernel_launch(void* const* d_in, const int* in_sizes, int n_in,
                              void* d_out, int out_size)
{
    const float* x       = (const float*)d_in[0];
    const float* Wr_in   = (const float*)d_in[2];
    const float* Wr_proc = (const float*)d_in[3];
    const float* Wr_out  = (const float*)d_in[4];
    const float* WrO_in  = (const float*)d_in[5];
    const float* WrO_proc= (const float*)d_in[6];
    const float* WrO_out = (const float*)d_in[7];
    const float* Wq_in   = (const float*)d_in[8];
    const float* vq      = (const float*)d_in[9];
    const float* Wq_out  = (const float*)d_in[10];
    const float* Wk_in   = (const float*)d_in[11];
    const float* vk      = (const float*)d_in[12];
    const float* Wk_out  = (const float*)d_in[13];
    const float* Wv_in   = (const float*)d_in[14];
    const float* vv      = (const float*)d_in[15];
    const float* Wv_out  = (const float*)d_in[16];
    const float* Wo_in   = (const float*)d_in[17];
    const float* vo      = (const float*)d_in[18];
    const float* Wo_out  = (const float*)d_in[19];
    float* out = (float*)d_out;

    float *h, *Q, *Kc, *V, *O, *inw, *outw;
    int* pidx;
    __nv_bfloat16 *whi, *wlo, *xhi, *xlo, *hhi, *hlo;
    cudaGetSymbolAddress((void**)&h,    g_h);
    cudaGetSymbolAddress((void**)&Q,    g_Q);
    cudaGetSymbolAddress((void**)&Kc,   g_Kc);
    cudaGetSymbolAddress((void**)&V,    g_V);
    cudaGetSymbolAddress((void**)&O,    g_O);
    cudaGetSymbolAddress((void**)&inw,  g_inw);
    cudaGetSymbolAddress((void**)&outw, g_outw);
    cudaGetSymbolAddress((void**)&pidx, g_pidx);
    cudaGetSymbolAddress((void**)&whi,  g_whi);
    cudaGetSymbolAddress((void**)&wlo,  g_wlo);
    cudaGetSymbolAddress((void**)&xhi,  g_xhi);
    cudaGetSymbolAddress((void**)&xlo,  g_xlo);
    cudaGetSymbolAddress((void**)&hhi,  g_hhi);
    cudaGetSymbolAddress((void**)&hlo,  g_hlo);

    cudaFuncSetAttribute(circuit_gemm_tc,
                         cudaFuncAttributeMaxDynamicSharedMemorySize,
                         SMEM_GEMM_BYTES);

    dim3 gGemm(DIM / 128, TOK / 128);     // (8, 32)
    dim3 gPrep(DIM / 32, KTOT / 32);      // (32, 256)
    int  gSplit = TOK * DIM / (256 * 4);  // 4096

    auto gemm = [&](const __nv_bfloat16* ah, const __nv_bfloat16* al,
                    const float* W, const float* wg, float* o) {
        prep_w_kernel<<<gPrep, 256>>>(W, whi, wlo);
        circuit_gemm_tc<<<gGemm, 512, SMEM_GEMM_BYTES>>>(ah, al, whi, wlo, wg, o);
    };

    // Router on x + x split
    router_kernel<<<TOK, 128>>>(x, Wr_in, Wr_proc, Wr_out, inw, pidx, outw);
    split_kernel<<<gSplit, 256>>>(x, xhi, xlo);

    // Q circuit
    gemm(xhi, xlo, Wq_in, inw, h);
    householder_kernel<<<TOK, 256>>>(h, vq, pidx, hhi, hlo);
    gemm(hhi, hlo, Wq_out, outw, Q);

    // K circuit
    gemm(xhi, xlo, Wk_in, inw, h);
    householder_kernel<<<TOK, 256>>>(h, vk, pidx, hhi, hlo);
    gemm(hhi, hlo, Wk_out, outw, Kc);

    // V circuit
    gemm(xhi, xlo, Wv_in, inw, h);
    householder_kernel<<<TOK, 256>>>(h, vv, pidx, hhi, hlo);
    gemm(hhi, hlo, Wv_out, outw, V);

    // Attention
    attn_kernel<<<dim3(SEQ / 8, NBATCH * NH), 256>>>(Q, Kc, V, O);

    // Router on O + output circuit (reuse x split buffers)
    router_kernel<<<TOK, 128>>>(O, WrO_in, WrO_proc, WrO_out, inw, pidx, outw);
    split_kernel<<<gSplit, 256>>>(O, xhi, xlo);
    gemm(xhi, xlo, Wo_in, inw, h);
    householder_kernel<<<TOK, 256>>>(h, vo, pidx, hhi, hlo);
    gemm(hhi, hlo, Wo_out, outw, out);

    (void)in_sizes; (void)n_in; (void)out_size;
}